// round 5
// baseline (speedup 1.0000x reference)
#include <cuda_runtime.h>
#include <math.h>
#include <stdint.h>

// ------------------------------------------------------------------
// Scratch (device globals; no allocation allowed)
// Arena lifetime-aliased: h1/d2 share, h2/d1 share.
// ------------------------------------------------------------------
__device__ float g_arena[121634816];
__device__ float g_wtp[32768];       // 1x1 SIMT [k][m]
__device__ float g_w1hi[6144];       // conv1  [m][k] tf32 hi/lo
__device__ float g_w1lo[6144];
__device__ float g_w2hi[524288];     // conv2  [m][k]
__device__ float g_w2lo[524288];
__device__ float g_w3hi[2097152];    // conv3  [m][k]
__device__ float g_w3lo[2097152];
__device__ float g_wd1hi[262144];    // convT1 [par][o][k]
__device__ float g_wd2hi[524288];    // convT2 [par][o][k]
__device__ float g_vqpart[256];

// ------------------------------------------------------------------
// Helpers
// ------------------------------------------------------------------
__device__ __forceinline__ float tf32r(float v) {
    uint32_t u;
    asm("cvt.rna.tf32.f32 %0, %1;" : "=r"(u) : "f"(v));
    return __uint_as_float(u);
}

__device__ __forceinline__ void mma8(float* d, const float* a, const float* b) {
    asm volatile(
        "mma.sync.aligned.m16n8k8.row.col.f32.tf32.tf32.f32 "
        "{%0,%1,%2,%3},{%4,%5,%6,%7},{%8,%9},{%0,%1,%2,%3};"
        : "+f"(d[0]), "+f"(d[1]), "+f"(d[2]), "+f"(d[3])
        : "r"(__float_as_uint(a[0])), "r"(__float_as_uint(a[1])),
          "r"(__float_as_uint(a[2])), "r"(__float_as_uint(a[3])),
          "r"(__float_as_uint(b[0])), "r"(__float_as_uint(b[1])));
}

// ------------------------------------------------------------------
// Weight transforms
// ------------------------------------------------------------------
__global__ void wt_fwd_k(const float* __restrict__ w, float* __restrict__ wt,
                         int Cout, int CK) {
    int idx = blockIdx.x * 256 + threadIdx.x;
    if (idx >= Cout * CK) return;
    int co = idx / CK;
    int k  = idx - co * CK;
    wt[k * Cout + co] = w[idx];
}

__global__ void split_tf32_k(const float* __restrict__ w, float* __restrict__ hi,
                             float* __restrict__ lo, int n) {
    int i = blockIdx.x * 256 + threadIdx.x;
    if (i >= n) return;
    float v = w[i];
    float h = tf32r(v);
    hi[i] = h;
    lo[i] = tf32r(v - h);
}

// convT: w[i][o][kh][kw] -> [par][o][ci*4+dh*2+dw], tf32 hi only (decoder 1x)
__global__ void wt_trm_k(const float* __restrict__ w, float* __restrict__ hi,
                         int Cin, int Cout) {
    int per = Cout * Cin * 4;
    int total = 4 * per;
    int idx = blockIdx.x * 256 + threadIdx.x;
    if (idx >= total) return;
    int par = idx / per;
    int rem = idx - par * per;
    int o = rem / (Cin * 4);
    int kidx = rem - o * Cin * 4;
    int ci = kidx >> 2, dh = (kidx >> 1) & 1, dw = kidx & 1;
    int py = par >> 1, px = par & 1;
    int kh = 2 * dh + 1 - py;
    int kw = 2 * dw + 1 - px;
    hi[idx] = tf32r(w[((ci * Cout + o) * 4 + kh) * 4 + kw]);
}

// ------------------------------------------------------------------
// Warp-MMA (mma.sync tf32) implicit GEMM:
//   C[m][p] = sum_k W[m][k] * X[p][k]
// BM=128, BN=128, BK=16; 8 warps (2x4), warp tile 64x32, 4x4 m16n8k8 tiles.
// MODE 0: stride-2 4x4 conv (k = ci*16 + kh*4 + kw), chunk c <-> ci=c
// MODE 2: transpose-conv parity class (k = ci*4 + dh*2 + dw), scatter write
// SPLITS 3: 3xTF32 (hi*hi + lo*hi + hi*lo); SPLITS 1: plain tf32
// smem: 2 stages of { Ahi [16][136] (+Alo), Bhi [16][136] (+Blo) } floats
// ------------------------------------------------------------------
struct MP {
    const float* x;
    const float* whi;
    const float* wlo;
    const float* bias;
    float* out;
    int Cin, Hin, Win, Mtot, Hout, Wout, K, sHWo, sW, py, px;
};

template <int MODE, int SPLITS, int ACT>
__global__ __launch_bounds__(256) void mma_igemm(MP g) {
    extern __shared__ __align__(16) float sm[];
    constexpr int LD = 136;
    constexpr int AHI = 0;
    constexpr int ALO = 16 * LD;                       // valid when SPLITS==3
    constexpr int BHI = (SPLITS == 3 ? 2 : 1) * 16 * LD;
    constexpr int BLO = BHI + 16 * LD;
    constexpr int STAGE = (SPLITS == 3 ? 4 : 2) * 16 * LD;

    const int t = threadIdx.x;
    const int lane = t & 31;
    const int wid = t >> 5;
    const int p0 = blockIdx.x * 128;
    const int m0 = blockIdx.y * 128;

    // loader role: lm = row (m for A, p for B), kq = k sub-offset {0,8}
    const int lm = t & 127;
    const int kq = (t >> 7) * 8;

    // im2col decode for p = p0 + lm (fixed per thread)
    const int p = p0 + lm;
    const int n = p >> g.sHWo;
    const int rem = p & ((1 << g.sHWo) - 1);
    const int ho = rem >> g.sW, wo = rem & ((1 << g.sW) - 1);
    const float* __restrict__ xn = g.x + (size_t)n * g.Cin * g.Hin * g.Win;
    const int HW = g.Hin * g.Win;

    int rowoff[4], iwv[4];
    bool okh[4], okw[4];
    if (MODE == 0) {
#pragma unroll
        for (int kh = 0; kh < 4; kh++) {
            int ih = 2 * ho - 1 + kh;
            okh[kh] = (unsigned)ih < (unsigned)g.Hin;
            rowoff[kh] = ih * g.Win;
        }
#pragma unroll
        for (int kw = 0; kw < 4; kw++) {
            int iw = 2 * wo - 1 + kw;
            okw[kw] = (unsigned)iw < (unsigned)g.Win;
            iwv[kw] = iw;
        }
    } else {
#pragma unroll
        for (int dh = 0; dh < 2; dh++) {
            int ih = ho + g.py - dh;
            okh[dh] = (unsigned)ih < (unsigned)g.Hin;
            rowoff[dh] = ih * g.Win;
        }
#pragma unroll
        for (int dw = 0; dw < 2; dw++) {
            int iw = wo + g.px - dw;
            okw[dw] = (unsigned)iw < (unsigned)g.Win;
            iwv[dw] = iw;
        }
    }

    // warp tile position
    const int wm = (wid >> 2) * 64;   // warp m offset (0 / 64)
    const int wn = (wid & 3) * 32;    // warp n offset
    const int gp = lane >> 2;         // group id 0..7
    const int tg = lane & 3;          // thread-in-group 0..3

    float acc[4][4][4];
#pragma unroll
    for (int mi = 0; mi < 4; mi++)
#pragma unroll
        for (int ni = 0; ni < 4; ni++)
#pragma unroll
            for (int r = 0; r < 4; r++) acc[mi][ni][r] = 0.f;

    // prefetch registers
    float ah[8], alr[8], bh[8], blr[8];

    auto ldg_chunk = [&](int c) {
        const float* wp = g.whi + (size_t)(m0 + lm) * g.K + (c << 4) + kq;
        float4 q0 = *(const float4*)wp;
        float4 q1 = *(const float4*)(wp + 4);
        ah[0] = q0.x; ah[1] = q0.y; ah[2] = q0.z; ah[3] = q0.w;
        ah[4] = q1.x; ah[5] = q1.y; ah[6] = q1.z; ah[7] = q1.w;
        if (SPLITS == 3) {
            const float* wl = g.wlo + (size_t)(m0 + lm) * g.K + (c << 4) + kq;
            float4 r0 = *(const float4*)wl;
            float4 r1 = *(const float4*)(wl + 4);
            alr[0] = r0.x; alr[1] = r0.y; alr[2] = r0.z; alr[3] = r0.w;
            alr[4] = r1.x; alr[5] = r1.y; alr[6] = r1.z; alr[7] = r1.w;
        }
        if (MODE == 0) {
            const float* bp = xn + (size_t)c * HW;
#pragma unroll
            for (int j = 0; j < 8; j++) {
                int tap = kq + j;
                int kh = tap >> 2, kw = tap & 3;
                float v = (okh[kh] && okw[kw]) ? bp[rowoff[kh] + iwv[kw]] : 0.f;
                float h = tf32r(v);
                bh[j] = h;
                if (SPLITS == 3) blr[j] = tf32r(v - h);
            }
        } else {
#pragma unroll
            for (int j = 0; j < 8; j++) {
                int tap = kq + j;
                int cl = tap >> 2, dd = tap & 3;
                int dh = dd >> 1, dw = dd & 1;
                const float* bp = xn + (size_t)(c * 4 + cl) * HW;
                float v = (okh[dh] && okw[dw]) ? bp[rowoff[dh] + iwv[dw]] : 0.f;
                float h = tf32r(v);
                bh[j] = h;
                if (SPLITS == 3) blr[j] = tf32r(v - h);
            }
        }
    };

    auto sts_chunk = [&](int s) {
        float* S = sm + s * STAGE;
#pragma unroll
        for (int j = 0; j < 8; j++) {
            S[AHI + (kq + j) * LD + lm] = ah[j];
            S[BHI + (kq + j) * LD + lm] = bh[j];
            if (SPLITS == 3) {
                S[ALO + (kq + j) * LD + lm] = alr[j];
                S[BLO + (kq + j) * LD + lm] = blr[j];
            }
        }
    };

    auto compute = [&](int s) {
        const float* S = sm + s * STAGE;
#pragma unroll
        for (int ks = 0; ks < 2; ks++) {
            const int kb = ks * 8;
            float a[4][4], b[4][2];
            float a2[4][4], b2[4][2];
#pragma unroll
            for (int mi = 0; mi < 4; mi++) {
                int mr = wm + mi * 16 + gp;
                a[mi][0] = S[AHI + (kb + tg) * LD + mr];
                a[mi][1] = S[AHI + (kb + tg) * LD + mr + 8];
                a[mi][2] = S[AHI + (kb + tg + 4) * LD + mr];
                a[mi][3] = S[AHI + (kb + tg + 4) * LD + mr + 8];
                if (SPLITS == 3) {
                    a2[mi][0] = S[ALO + (kb + tg) * LD + mr];
                    a2[mi][1] = S[ALO + (kb + tg) * LD + mr + 8];
                    a2[mi][2] = S[ALO + (kb + tg + 4) * LD + mr];
                    a2[mi][3] = S[ALO + (kb + tg + 4) * LD + mr + 8];
                }
            }
#pragma unroll
            for (int ni = 0; ni < 4; ni++) {
                int pc = wn + ni * 8 + gp;
                b[ni][0] = S[BHI + (kb + tg) * LD + pc];
                b[ni][1] = S[BHI + (kb + tg + 4) * LD + pc];
                if (SPLITS == 3) {
                    b2[ni][0] = S[BLO + (kb + tg) * LD + pc];
                    b2[ni][1] = S[BLO + (kb + tg + 4) * LD + pc];
                }
            }
#pragma unroll
            for (int mi = 0; mi < 4; mi++)
#pragma unroll
                for (int ni = 0; ni < 4; ni++)
                    mma8(acc[mi][ni], a[mi], b[ni]);
            if (SPLITS == 3) {
#pragma unroll
                for (int mi = 0; mi < 4; mi++)
#pragma unroll
                    for (int ni = 0; ni < 4; ni++)
                        mma8(acc[mi][ni], a2[mi], b[ni]);
#pragma unroll
                for (int mi = 0; mi < 4; mi++)
#pragma unroll
                    for (int ni = 0; ni < 4; ni++)
                        mma8(acc[mi][ni], a[mi], b2[ni]);
            }
        }
    };

    const int nc = g.K >> 4;
    ldg_chunk(0);
    sts_chunk(0);
    __syncthreads();
    for (int c = 0; c < nc; c++) {
        const int s = c & 1;
        if (c + 1 < nc) ldg_chunk(c + 1);
        compute(s);
        if (c + 1 < nc) sts_chunk(s ^ 1);
        __syncthreads();
    }

    // epilogue
    const int HWo = 1 << g.sHWo;
    const int nn = p0 >> g.sHWo;
    const int rem0 = p0 & (HWo - 1);
#pragma unroll
    for (int mi = 0; mi < 4; mi++) {
        const int mA = m0 + wm + mi * 16 + gp;
        const int mB = mA + 8;
        const float bA = g.bias[mA];
        const float bB = g.bias[mB];
#pragma unroll
        for (int ni = 0; ni < 4; ni++) {
            const int col = wn + ni * 8 + 2 * tg;
            float v0 = acc[mi][ni][0] + bA;
            float v1 = acc[mi][ni][1] + bA;
            float v2 = acc[mi][ni][2] + bB;
            float v3 = acc[mi][ni][3] + bB;
            if (ACT) {
                v0 = fmaxf(v0, 0.f); v1 = fmaxf(v1, 0.f);
                v2 = fmaxf(v2, 0.f); v3 = fmaxf(v3, 0.f);
            }
            if (MODE == 0) {
                float2 q0 = {v0, v1}, q1 = {v2, v3};
                *(float2*)&g.out[((size_t)nn * g.Mtot + mA) * HWo + rem0 + col] = q0;
                *(float2*)&g.out[((size_t)nn * g.Mtot + mB) * HWo + rem0 + col] = q1;
            } else {
                int rr = rem0 + col;
                int hh = rr >> g.sW, ww = rr & ((1 << g.sW) - 1);
                size_t r0 = ((size_t)nn * g.Mtot + mA) * g.Hout + 2 * hh + g.py;
                g.out[r0 * g.Wout + 2 * ww + g.px] = v0;
                g.out[r0 * g.Wout + 2 * (ww + 1) + g.px] = v1;
                size_t r1 = ((size_t)nn * g.Mtot + mB) * g.Hout + 2 * hh + g.py;
                g.out[r1 * g.Wout + 2 * ww + g.px] = v2;
                g.out[r1 * g.Wout + 2 * (ww + 1) + g.px] = v3;
            }
        }
    }
}

// ------------------------------------------------------------------
// SIMT implicit GEMM (1x1 conv only): C[m][p] = sum_k wt[k][m]*B[k][p]
// ------------------------------------------------------------------
struct GP {
    const float* x;
    const float* wt;
    const float* bias;
    float* out;
    int Cin, Hin, Win;
    int M;
    int K;
    int sHWo;
    int sW;
};

template <int ACT>
__global__ __launch_bounds__(256) void igemm1x1(GP g) {
    __shared__ __align__(16) float As[16][64];
    __shared__ __align__(16) float Bs[16][64];
    const int t = threadIdx.x;
    const int p0 = blockIdx.x * 64;
    const int m0 = blockIdx.y * 64;
    const int lc = t & 63, lr = t >> 6;
    const int tx = t & 15, ty = t >> 4;

    const int pB = p0 + lc;
    const int nB = pB >> g.sHWo;
    const int remB = pB & ((1 << g.sHWo) - 1);
    const float* __restrict__ xn = g.x + (size_t)nB * g.Cin * g.Hin * g.Win;

    float acc[4][4];
#pragma unroll
    for (int i = 0; i < 4; i++)
#pragma unroll
        for (int j = 0; j < 4; j++) acc[i][j] = 0.f;

    for (int k0 = 0; k0 < g.K; k0 += 16) {
#pragma unroll
        for (int j = 0; j < 4; j++) {
            int r = lr + 4 * j;
            As[r][lc] = g.wt[(size_t)(k0 + r) * g.M + m0 + lc];
            Bs[r][lc] = xn[(size_t)(k0 + r) * g.Win + remB];
        }
        __syncthreads();
#pragma unroll
        for (int kk = 0; kk < 16; kk++) {
            float4 a4 = *(const float4*)&As[kk][ty * 4];
            float4 b4 = *(const float4*)&Bs[kk][tx * 4];
            float av[4] = {a4.x, a4.y, a4.z, a4.w};
            float bv[4] = {b4.x, b4.y, b4.z, b4.w};
#pragma unroll
            for (int i = 0; i < 4; i++)
#pragma unroll
                for (int j = 0; j < 4; j++) acc[i][j] += av[i] * bv[j];
        }
        __syncthreads();
    }

    const int HWo = 1 << g.sHWo;
#pragma unroll
    for (int j = 0; j < 4; j++) {
        int p = p0 + tx * 4 + j;
        int nn = p >> g.sHWo;
        int rm = p & (HWo - 1);
#pragma unroll
        for (int i = 0; i < 4; i++) {
            int m = m0 + ty * 4 + i;
            float v = acc[i][j] + g.bias[m];
            if (ACT == 1) v = fmaxf(v, 0.f);
            g.out[((size_t)nn * g.M + m) * HWo + rm] = v;
        }
    }
}

// ------------------------------------------------------------------
// VQ + loss
// ------------------------------------------------------------------
__global__ __launch_bounds__(128) void vq_kernel(
    const float* __restrict__ ze, const float* __restrict__ emb,
    float* __restrict__ zq, float* __restrict__ partial) {
    __shared__ float es[128 * 64];
    __shared__ float red[128];
    const int t = threadIdx.x;
    const int pos = blockIdx.x * 128 + t;
    const int n = pos >> 10;
    const int hw = pos & 1023;

    float xv[64];
    const float* zp = ze + (size_t)n * 65536 + hw;
#pragma unroll
    for (int d = 0; d < 64; d++) xv[d] = zp[(size_t)d * 1024];

    float best = 3.0e38f;
    int bidx = 0;
    for (int c0 = 0; c0 < 512; c0 += 128) {
        __syncthreads();
        for (int i = t; i < 128 * 64; i += 128) es[i] = emb[c0 * 64 + i];
        __syncthreads();
        for (int c = 0; c < 128; c++) {
            float d2 = 0.f;
#pragma unroll
            for (int d = 0; d < 64; d++) {
                float df = xv[d] - es[c * 64 + d];
                d2 += df * df;
            }
            if (d2 < best) { best = d2; bidx = c0 + c; }
        }
    }
    const float* e = emb + (size_t)bidx * 64;
    float* q = zq + (size_t)n * 65536 + hw;
#pragma unroll
    for (int d = 0; d < 64; d++) q[(size_t)d * 1024] = e[d];

    red[t] = best;
    __syncthreads();
    for (int s = 64; s > 0; s >>= 1) {
        if (t < s) red[t] += red[t + s];
        __syncthreads();
    }
    if (t == 0) partial[blockIdx.x] = red[0];
}

__global__ void vq_loss_kernel(const float* __restrict__ partial,
                               float* __restrict__ out_loss) {
    __shared__ float red[256];
    int t = threadIdx.x;
    red[t] = partial[t];
    __syncthreads();
    for (int s = 128; s > 0; s >>= 1) {
        if (t < s) red[t] += red[t + s];
        __syncthreads();
    }
    if (t == 0) out_loss[0] = red[0] * (2.0f / 2097152.0f);
}

// ------------------------------------------------------------------
// convT3 direct + sigmoid
// ------------------------------------------------------------------
__global__ __launch_bounds__(128) void convt3_kernel(
    const float* __restrict__ in, const float* __restrict__ w,
    const float* __restrict__ b, float* __restrict__ out) {
    __shared__ float ws[6144];
    for (int i = threadIdx.x; i < 6144; i += 128) ws[i] = w[i];
    __syncthreads();

    const int xq = threadIdx.x;
    const int yq = blockIdx.y;
    const int z = blockIdx.z;
    const int n = z >> 2;
    const int py = (z >> 1) & 1, px = z & 1;

    float a0 = b[0], a1 = b[1], a2 = b[2];
    const float* xn = in + (size_t)n * 128 * 128 * 128;
    for (int i = 0; i < 128; i++) {
        const float* xi = xn + (size_t)i * 16384;
#pragma unroll
        for (int dh = 0; dh < 2; dh++) {
#pragma unroll
            for (int dw = 0; dw < 2; dw++) {
                int h = yq + py - dh;
                int wv = xq + px - dw;
                if ((unsigned)h < 128u && (unsigned)wv < 128u) {
                    float xvv = xi[h * 128 + wv];
                    int kh = 2 * dh + 1 - py;
                    int kw = 2 * dw + 1 - px;
                    int base = i * 48 + kh * 4 + kw;
                    a0 += xvv * ws[base];
                    a1 += xvv * ws[base + 16];
                    a2 += xvv * ws[base + 32];
                }
            }
        }
    }
    int y = 2 * yq + py;
    int xx = 2 * xq + px;
    size_t o = ((size_t)n * 3) * 65536 + (size_t)y * 256 + xx;
    out[o] = 1.f / (1.f + expf(-a0));
    out[o + 65536] = 1.f / (1.f + expf(-a1));
    out[o + 131072] = 1.f / (1.f + expf(-a2));
}

// ------------------------------------------------------------------
// Launch
// ------------------------------------------------------------------
extern "C" void kernel_launch(void* const* d_in, const int* in_sizes, int n_in,
                              void* d_out, int out_size) {
    (void)in_sizes; (void)n_in; (void)out_size;
    const float* x   = (const float*)d_in[0];
    const float* ew1 = (const float*)d_in[1];
    const float* eb1 = (const float*)d_in[2];
    const float* ew2 = (const float*)d_in[3];
    const float* eb2 = (const float*)d_in[4];
    const float* ew3 = (const float*)d_in[5];
    const float* eb3 = (const float*)d_in[6];
    const float* pw  = (const float*)d_in[7];
    const float* pb  = (const float*)d_in[8];
    const float* emb = (const float*)d_in[9];
    const float* dw1 = (const float*)d_in[10];
    const float* db1 = (const float*)d_in[11];
    const float* dw2 = (const float*)d_in[12];
    const float* db2 = (const float*)d_in[13];
    const float* dw3 = (const float*)d_in[14];
    const float* db3 = (const float*)d_in[15];
    float* out = (float*)d_out;

    float *arena, *wtp, *part;
    float *w1hi, *w1lo, *w2hi, *w2lo, *w3hi, *w3lo, *wd1hi, *wd2hi;
    cudaGetSymbolAddress((void**)&arena, g_arena);
    cudaGetSymbolAddress((void**)&wtp, g_wtp);
    cudaGetSymbolAddress((void**)&w1hi, g_w1hi);
    cudaGetSymbolAddress((void**)&w1lo, g_w1lo);
    cudaGetSymbolAddress((void**)&w2hi, g_w2hi);
    cudaGetSymbolAddress((void**)&w2lo, g_w2lo);
    cudaGetSymbolAddress((void**)&w3hi, g_w3hi);
    cudaGetSymbolAddress((void**)&w3lo, g_w3lo);
    cudaGetSymbolAddress((void**)&wd1hi, g_wd1hi);
    cudaGetSymbolAddress((void**)&wd2hi, g_wd2hi);
    cudaGetSymbolAddress((void**)&part, g_vqpart);

    float* h1  = arena;
    float* d2b = arena;
    float* h2  = arena + 67108864;
    float* d1b = arena + 67108864;
    float* h3  = arena + 100663296;
    float* ze  = arena + 117440512;
    float* zq  = arena + 119537664;

    const int SM3 = 2 * 4 * 16 * 136 * 4;  // 69632 B (SPLITS=3)
    const int SM1 = 2 * 2 * 16 * 136 * 4;  // 34816 B (SPLITS=1)
    cudaFuncSetAttribute(mma_igemm<0, 3, 1>,
                         cudaFuncAttributeMaxDynamicSharedMemorySize, SM3);
    cudaFuncSetAttribute(mma_igemm<2, 1, 1>,
                         cudaFuncAttributeMaxDynamicSharedMemorySize, SM1);

    // weight transforms
    wt_fwd_k<<<(64 * 512 + 255) / 256, 256>>>(pw, wtp, 64, 512);
    split_tf32_k<<<24, 256>>>(ew1, w1hi, w1lo, 6144);
    split_tf32_k<<<2048, 256>>>(ew2, w2hi, w2lo, 524288);
    split_tf32_k<<<8192, 256>>>(ew3, w3hi, w3lo, 2097152);
    wt_trm_k<<<1024, 256>>>(dw1, wd1hi, 64, 256);
    wt_trm_k<<<2048, 256>>>(dw2, wd2hi, 256, 128);

    MP m;
    m.py = 0; m.px = 0; m.wlo = w1lo;

    // conv1 (3xTF32 mma): x[32,3,256,256] -> h1[32,128,128,128]
    m.x = x; m.whi = w1hi; m.wlo = w1lo; m.bias = eb1; m.out = h1;
    m.Cin = 3; m.Hin = 256; m.Win = 256; m.Mtot = 128;
    m.Hout = 128; m.Wout = 128; m.K = 48; m.sHWo = 14; m.sW = 7;
    mma_igemm<0, 3, 1><<<dim3(4096, 1), 256, SM3>>>(m);

    // conv2 (3xTF32): h1 -> h2[32,256,64,64]
    m.x = h1; m.whi = w2hi; m.wlo = w2lo; m.bias = eb2; m.out = h2;
    m.Cin = 128; m.Hin = 128; m.Win = 128; m.Mtot = 256;
    m.Hout = 64; m.Wout = 64; m.K = 2048; m.sHWo = 12; m.sW = 6;
    mma_igemm<0, 3, 1><<<dim3(1024, 2), 256, SM3>>>(m);

    // conv3 (3xTF32): h2 -> h3[32,512,32,32]
    m.x = h2; m.whi = w3hi; m.wlo = w3lo; m.bias = eb3; m.out = h3;
    m.Cin = 256; m.Hin = 64; m.Win = 64; m.Mtot = 512;
    m.Hout = 32; m.Wout = 32; m.K = 4096; m.sHWo = 10; m.sW = 5;
    mma_igemm<0, 3, 1><<<dim3(256, 4), 256, SM3>>>(m);

    // pre-VQ 1x1 (SIMT fp32): h3 -> ze
    GP g;
    g.x = h3; g.wt = wtp; g.bias = pb; g.out = ze;
    g.Cin = 512; g.Hin = 1; g.Win = 1024; g.M = 64;
    g.K = 512; g.sHWo = 10; g.sW = 0;
    igemm1x1<0><<<dim3(32768 / 64, 1), 256>>>(g);

    // VQ
    vq_kernel<<<256, 128>>>(ze, emb, zq, part);
    vq_loss_kernel<<<1, 256>>>(part, out + 6291456);

    // convT1 (1xTF32): zq -> d1[32,256,64,64]
    for (int par = 0; par < 4; par++) {
        m.x = zq; m.whi = wd1hi + (size_t)par * 65536; m.wlo = wd1hi;
        m.bias = db1; m.out = d1b;
        m.Cin = 64; m.Hin = 32; m.Win = 32; m.Mtot = 256;
        m.Hout = 64; m.Wout = 64; m.K = 256; m.sHWo = 10; m.sW = 5;
        m.py = par >> 1; m.px = par & 1;
        mma_igemm<2, 1, 1><<<dim3(256, 2), 256, SM1>>>(m);
    }

    // convT2 (1xTF32): d1 -> d2[32,128,128,128]
    for (int par = 0; par < 4; par++) {
        m.x = d1b; m.whi = wd2hi + (size_t)par * 131072; m.wlo = wd2hi;
        m.bias = db2; m.out = d2b;
        m.Cin = 256; m.Hin = 64; m.Win = 64; m.Mtot = 128;
        m.Hout = 128; m.Wout = 128; m.K = 1024; m.sHWo = 12; m.sW = 6;
        m.py = par >> 1; m.px = par & 1;
        mma_igemm<2, 1, 1><<<dim3(1024, 1), 256, SM1>>>(m);
    }

    // convT3 direct + sigmoid
    convt3_kernel<<<dim3(1, 128, 128), 128>>>(d2b, dw3, db3, out);
}

// round 7
// speedup vs baseline: 1.5418x; 1.5418x over previous
#include <cuda_runtime.h>
#include <math.h>
#include <stdint.h>

// ------------------------------------------------------------------
// Scratch (device globals). Arena lifetime-aliased: h1/d2, h2/d1.
// ------------------------------------------------------------------
__device__ float g_arena[121634816];
__device__ float g_wtp[32768];       // 1x1 SIMT [k][m]
__device__ float g_w1hi[6144];       // conv1  [m][k] tf32 hi/lo
__device__ float g_w1lo[6144];
__device__ float g_w2hi[524288];     // conv2  [m][k]
__device__ float g_w2lo[524288];
__device__ float g_w3hi[2097152];    // conv3  [m][k]
__device__ float g_w3lo[2097152];
__device__ float g_wd1hi[262144];    // convT1 [par][o][k]
__device__ float g_wd2hi[524288];    // convT2 [par][o][k]
__device__ float g_vqpart[256];

// ------------------------------------------------------------------
// Helpers
// ------------------------------------------------------------------
__device__ __forceinline__ float tf32r(float v) {
    uint32_t u;
    asm("cvt.rna.tf32.f32 %0, %1;" : "=r"(u) : "f"(v));
    return __uint_as_float(u);
}
__device__ __forceinline__ uint32_t smem_u32(const void* p) {
    uint32_t a;
    asm("{ .reg .u64 t; cvta.to.shared.u64 t, %1; cvt.u32.u64 %0, t; }"
        : "=r"(a) : "l"(p));
    return a;
}
__device__ __forceinline__ void cpasync16(uint32_t dst, const void* src) {
    asm volatile("cp.async.cg.shared.global [%0], [%1], 16;"
                 :: "r"(dst), "l"(src));
}
#define CP_COMMIT() asm volatile("cp.async.commit_group;" ::: "memory")
#define CP_WAIT0()  asm volatile("cp.async.wait_group 0;" ::: "memory")

__device__ __forceinline__ void mma8(float* d, const float* a, const float* b) {
    asm volatile(
        "mma.sync.aligned.m16n8k8.row.col.f32.tf32.tf32.f32 "
        "{%0,%1,%2,%3},{%4,%5,%6,%7},{%8,%9},{%0,%1,%2,%3};"
        : "+f"(d[0]), "+f"(d[1]), "+f"(d[2]), "+f"(d[3])
        : "r"(__float_as_uint(a[0])), "r"(__float_as_uint(a[1])),
          "r"(__float_as_uint(a[2])), "r"(__float_as_uint(a[3])),
          "r"(__float_as_uint(b[0])), "r"(__float_as_uint(b[1])));
}

// ------------------------------------------------------------------
// Fused weight transforms (3 launches total so ncu lands on conv3)
// ------------------------------------------------------------------
__device__ __forceinline__ void trm_one(const float* w, float* hi, int idx,
                                        int Cin, int Cout) {
    int per = Cout * Cin * 4;
    int par = idx / per;
    int rem = idx - par * per;
    int o = rem / (Cin * 4);
    int kidx = rem - o * Cin * 4;
    int ci = kidx >> 2, dh = (kidx >> 1) & 1, dw = kidx & 1;
    int py = par >> 1, px = par & 1;
    int kh = 2 * dh + 1 - py;
    int kw = 2 * dw + 1 - px;
    hi[idx] = tf32r(w[((ci * Cout + o) * 4 + kh) * 4 + kw]);
}

// w1 split (6144) | pw fwd (32768) | dw1 trm (262144) | dw2 trm (524288)
__global__ void xform_misc(const float* __restrict__ ew1, float* __restrict__ w1hi,
                           float* __restrict__ w1lo,
                           const float* __restrict__ pw, float* __restrict__ wtp,
                           const float* __restrict__ dw1, float* __restrict__ wd1hi,
                           const float* __restrict__ dw2, float* __restrict__ wd2hi) {
    int idx = blockIdx.x * 256 + threadIdx.x;
    if (idx < 6144) {
        float v = ew1[idx];
        float h = tf32r(v);
        w1hi[idx] = h;
        w1lo[idx] = tf32r(v - h);
    } else if (idx < 6144 + 32768) {
        int i = idx - 6144;               // Cout=64, CK=512
        int co = i / 512, k = i - co * 512;
        wtp[k * 64 + co] = pw[i];
    } else if (idx < 6144 + 32768 + 262144) {
        trm_one(dw1, wd1hi, idx - 38912, 64, 256);
    } else if (idx < 6144 + 32768 + 262144 + 524288) {
        trm_one(dw2, wd2hi, idx - 301056, 256, 128);
    }
}

__global__ void split_tf32_k(const float* __restrict__ w, float* __restrict__ hi,
                             float* __restrict__ lo, int n) {
    int i = blockIdx.x * 256 + threadIdx.x;
    if (i >= n) return;
    float v = w[i];
    float h = tf32r(v);
    hi[i] = h;
    lo[i] = tf32r(v - h);
}

// ------------------------------------------------------------------
// Warp-MMA (mma.sync tf32) implicit GEMM: C[m][p] = sum_k W[m][k]*X[p][k]
// BM=128, BN=128, BK=16; 8 warps (2x4), warp tile 64x32.
// A via cp.async to smem [m][k] rows (LDA=20, conflict-free fragment LDS);
// B gathered to regs -> sts [k][p] (LDB=136).
// MODE 0: stride-2 4x4 conv; MODE 2: transpose-conv parity (scatter write).
// SPLITS 3: 3xTF32; SPLITS 1: plain tf32.
// ------------------------------------------------------------------
struct MP {
    const float* x;
    const float* whi;
    const float* wlo;
    const float* bias;
    float* out;
    int Cin, Hin, Win, Mtot, Hout, Wout, K, sHWo, sW, py, px;
};

template <int MODE, int SPLITS, int ACT>
__global__ __launch_bounds__(256, 2) void mma_igemm(MP g) {
    extern __shared__ __align__(16) float sm[];
    constexpr int LDA = 20;
    constexpr int LDB = 136;
    constexpr int AHI = 0;
    constexpr int ALO = 128 * LDA;
    constexpr int BHI = (SPLITS == 3 ? 2 : 1) * 128 * LDA;
    constexpr int BLO = BHI + 16 * LDB;
    constexpr int STAGE = BHI + (SPLITS == 3 ? 2 : 1) * 16 * LDB;

    const int t = threadIdx.x;
    const int lane = t & 31;
    const int wid = t >> 5;
    const int p0 = blockIdx.x * 128;
    const int m0 = blockIdx.y * 128;
    const uint32_t sbase = smem_u32(sm);

    // A cp.async role
    const int rmA = t >> 1;
    const int halfA = (t & 1) * 8;

    // B loader role
    const int lm = t & 127;
    const int kq = (t >> 7) * 8;

    // im2col decode for p = p0 + lm
    const int p = p0 + lm;
    const int n = p >> g.sHWo;
    const int rem = p & ((1 << g.sHWo) - 1);
    const int ho = rem >> g.sW, wo = rem & ((1 << g.sW) - 1);
    const float* __restrict__ xn = g.x + (size_t)n * g.Cin * g.Hin * g.Win;
    const int HW = g.Hin * g.Win;

    int rowoff[4], iwv[4];
    bool okh[4], okw[4];
    if (MODE == 0) {
#pragma unroll
        for (int kh = 0; kh < 4; kh++) {
            int ih = 2 * ho - 1 + kh;
            okh[kh] = (unsigned)ih < (unsigned)g.Hin;
            rowoff[kh] = ih * g.Win;
        }
#pragma unroll
        for (int kw = 0; kw < 4; kw++) {
            int iw = 2 * wo - 1 + kw;
            okw[kw] = (unsigned)iw < (unsigned)g.Win;
            iwv[kw] = iw;
        }
    } else {
#pragma unroll
        for (int dh = 0; dh < 2; dh++) {
            int ih = ho + g.py - dh;
            okh[dh] = (unsigned)ih < (unsigned)g.Hin;
            rowoff[dh] = ih * g.Win;
        }
#pragma unroll
        for (int dw = 0; dw < 2; dw++) {
            int iw = wo + g.px - dw;
            okw[dw] = (unsigned)iw < (unsigned)g.Win;
            iwv[dw] = iw;
        }
    }

    const int wm = (wid >> 2) * 64;
    const int wn = (wid & 3) * 32;
    const int gp = lane >> 2;
    const int tg = lane & 3;

    float acc[4][4][4];
#pragma unroll
    for (int mi = 0; mi < 4; mi++)
#pragma unroll
        for (int ni = 0; ni < 4; ni++)
#pragma unroll
            for (int r = 0; r < 4; r++) acc[mi][ni][r] = 0.f;

    float bh[8], blr[8];

    auto issueA = [&](int c, int s) {
        uint32_t d = sbase + (uint32_t)(s * STAGE + AHI + rmA * LDA + halfA) * 4;
        const float* srcH = g.whi + (size_t)(m0 + rmA) * g.K + (c << 4) + halfA;
        cpasync16(d, srcH);
        cpasync16(d + 16, srcH + 4);
        if (SPLITS == 3) {
            uint32_t d2 = d + (uint32_t)(ALO) * 4;
            const float* srcL =
                g.wlo + (size_t)(m0 + rmA) * g.K + (c << 4) + halfA;
            cpasync16(d2, srcL);
            cpasync16(d2 + 16, srcL + 4);
        }
    };

    auto gatherB = [&](int c) {
        if (MODE == 0) {
            const float* bp = xn + (size_t)c * HW;
#pragma unroll
            for (int j = 0; j < 8; j++) {
                int tap = kq + j;
                int kh = tap >> 2, kw = tap & 3;
                float v = (okh[kh] && okw[kw]) ? bp[rowoff[kh] + iwv[kw]] : 0.f;
                float h = tf32r(v);
                bh[j] = h;
                if (SPLITS == 3) blr[j] = tf32r(v - h);
            }
        } else {
#pragma unroll
            for (int j = 0; j < 8; j++) {
                int tap = kq + j;
                int cl = tap >> 2, dd = tap & 3;
                int dh = dd >> 1, dw = dd & 1;
                const float* bp = xn + (size_t)(c * 4 + cl) * HW;
                float v = (okh[dh] && okw[dw]) ? bp[rowoff[dh] + iwv[dw]] : 0.f;
                float h = tf32r(v);
                bh[j] = h;
                if (SPLITS == 3) blr[j] = tf32r(v - h);
            }
        }
    };

    auto stsB = [&](int s) {
        float* S = sm + s * STAGE;
#pragma unroll
        for (int j = 0; j < 8; j++) {
            S[BHI + (kq + j) * LDB + lm] = bh[j];
            if (SPLITS == 3) S[BLO + (kq + j) * LDB + lm] = blr[j];
        }
    };

    auto compute = [&](int s) {
        const float* S = sm + s * STAGE;
#pragma unroll
        for (int ks = 0; ks < 2; ks++) {
            const int kb = ks * 8;
            float b[4][2], b2[4][2];
#pragma unroll
            for (int ni = 0; ni < 4; ni++) {
                int pc = wn + ni * 8 + gp;
                b[ni][0] = S[BHI + (kb + tg) * LDB + pc];
                b[ni][1] = S[BHI + (kb + tg + 4) * LDB + pc];
                if (SPLITS == 3) {
                    b2[ni][0] = S[BLO + (kb + tg) * LDB + pc];
                    b2[ni][1] = S[BLO + (kb + tg + 4) * LDB + pc];
                }
            }
#pragma unroll
            for (int mi = 0; mi < 4; mi++) {
                const int mr = wm + mi * 16 + gp;
                float a[4];
                a[0] = S[AHI + mr * LDA + kb + tg];
                a[1] = S[AHI + (mr + 8) * LDA + kb + tg];
                a[2] = S[AHI + mr * LDA + kb + tg + 4];
                a[3] = S[AHI + (mr + 8) * LDA + kb + tg + 4];
#pragma unroll
                for (int ni = 0; ni < 4; ni++) mma8(acc[mi][ni], a, b[ni]);
                if (SPLITS == 3) {
                    float a2[4];
                    a2[0] = S[ALO + mr * LDA + kb + tg];
                    a2[1] = S[ALO + (mr + 8) * LDA + kb + tg];
                    a2[2] = S[ALO + mr * LDA + kb + tg + 4];
                    a2[3] = S[ALO + (mr + 8) * LDA + kb + tg + 4];
#pragma unroll
                    for (int ni = 0; ni < 4; ni++) mma8(acc[mi][ni], a2, b[ni]);
#pragma unroll
                    for (int ni = 0; ni < 4; ni++) mma8(acc[mi][ni], a, b2[ni]);
                }
            }
        }
    };

    const int nc = g.K >> 4;
    issueA(0, 0);
    CP_COMMIT();
    gatherB(0);
    stsB(0);
    CP_WAIT0();
    __syncthreads();
    for (int c = 0; c < nc; c++) {
        const int s = c & 1;
        if (c + 1 < nc) {
            issueA(c + 1, s ^ 1);
            CP_COMMIT();
            gatherB(c + 1);
        }
        compute(s);
        if (c + 1 < nc) {
            stsB(s ^ 1);
            CP_WAIT0();
        }
        __syncthreads();
    }

    // epilogue
    const int HWo = 1 << g.sHWo;
    const int nn = p0 >> g.sHWo;
    const int rem0 = p0 & (HWo - 1);
#pragma unroll
    for (int mi = 0; mi < 4; mi++) {
        const int mA = m0 + wm + mi * 16 + gp;
        const int mB = mA + 8;
        const float bA = g.bias[mA];
        const float bB = g.bias[mB];
#pragma unroll
        for (int ni = 0; ni < 4; ni++) {
            const int col = wn + ni * 8 + 2 * tg;
            float v0 = acc[mi][ni][0] + bA;
            float v1 = acc[mi][ni][1] + bA;
            float v2 = acc[mi][ni][2] + bB;
            float v3 = acc[mi][ni][3] + bB;
            if (ACT) {
                v0 = fmaxf(v0, 0.f); v1 = fmaxf(v1, 0.f);
                v2 = fmaxf(v2, 0.f); v3 = fmaxf(v3, 0.f);
            }
            if (MODE == 0) {
                float2 q0 = {v0, v1}, q1 = {v2, v3};
                *(float2*)&g.out[((size_t)nn * g.Mtot + mA) * HWo + rem0 + col] = q0;
                *(float2*)&g.out[((size_t)nn * g.Mtot + mB) * HWo + rem0 + col] = q1;
            } else {
                int rr = rem0 + col;
                int hh = rr >> g.sW, ww = rr & ((1 << g.sW) - 1);
                size_t r0 = ((size_t)nn * g.Mtot + mA) * g.Hout + 2 * hh + g.py;
                g.out[r0 * g.Wout + 2 * ww + g.px] = v0;
                g.out[r0 * g.Wout + 2 * (ww + 1) + g.px] = v1;
                size_t r1 = ((size_t)nn * g.Mtot + mB) * g.Hout + 2 * hh + g.py;
                g.out[r1 * g.Wout + 2 * ww + g.px] = v2;
                g.out[r1 * g.Wout + 2 * (ww + 1) + g.px] = v3;
            }
        }
    }
}

// ------------------------------------------------------------------
// SIMT implicit GEMM (1x1 conv only)
// ------------------------------------------------------------------
struct GP {
    const float* x;
    const float* wt;
    const float* bias;
    float* out;
    int Cin, Hin, Win, M, K, sHWo, sW;
};

template <int ACT>
__global__ __launch_bounds__(256) void igemm1x1(GP g) {
    __shared__ __align__(16) float As[16][64];
    __shared__ __align__(16) float Bs[16][64];
    const int t = threadIdx.x;
    const int p0 = blockIdx.x * 64;
    const int m0 = blockIdx.y * 64;
    const int lc = t & 63, lr = t >> 6;
    const int tx = t & 15, ty = t >> 4;

    const int pB = p0 + lc;
    const int nB = pB >> g.sHWo;
    const int remB = pB & ((1 << g.sHWo) - 1);
    const float* __restrict__ xn = g.x + (size_t)nB * g.Cin * g.Hin * g.Win;

    float acc[4][4];
#pragma unroll
    for (int i = 0; i < 4; i++)
#pragma unroll
        for (int j = 0; j < 4; j++) acc[i][j] = 0.f;

    for (int k0 = 0; k0 < g.K; k0 += 16) {
#pragma unroll
        for (int j = 0; j < 4; j++) {
            int r = lr + 4 * j;
            As[r][lc] = g.wt[(size_t)(k0 + r) * g.M + m0 + lc];
            Bs[r][lc] = xn[(size_t)(k0 + r) * g.Win + remB];
        }
        __syncthreads();
#pragma unroll
        for (int kk = 0; kk < 16; kk++) {
            float4 a4 = *(const float4*)&As[kk][ty * 4];
            float4 b4 = *(const float4*)&Bs[kk][tx * 4];
            float av[4] = {a4.x, a4.y, a4.z, a4.w};
            float bv[4] = {b4.x, b4.y, b4.z, b4.w};
#pragma unroll
            for (int i = 0; i < 4; i++)
#pragma unroll
                for (int j = 0; j < 4; j++) acc[i][j] += av[i] * bv[j];
        }
        __syncthreads();
    }

    const int HWo = 1 << g.sHWo;
#pragma unroll
    for (int j = 0; j < 4; j++) {
        int p = p0 + tx * 4 + j;
        int nn = p >> g.sHWo;
        int rm = p & (HWo - 1);
#pragma unroll
        for (int i = 0; i < 4; i++) {
            int m = m0 + ty * 4 + i;
            float v = acc[i][j] + g.bias[m];
            if (ACT == 1) v = fmaxf(v, 0.f);
            g.out[((size_t)nn * g.M + m) * HWo + rm] = v;
        }
    }
}

// ------------------------------------------------------------------
// VQ + loss
// ------------------------------------------------------------------
__global__ __launch_bounds__(128) void vq_kernel(
    const float* __restrict__ ze, const float* __restrict__ emb,
    float* __restrict__ zq, float* __restrict__ partial) {
    __shared__ float es[128 * 64];
    __shared__ float red[128];
    const int t = threadIdx.x;
    const int pos = blockIdx.x * 128 + t;
    const int n = pos >> 10;
    const int hw = pos & 1023;

    float xv[64];
    const float* zp = ze + (size_t)n * 65536 + hw;
#pragma unroll
    for (int d = 0; d < 64; d++) xv[d] = zp[(size_t)d * 1024];

    float best = 3.0e38f;
    int bidx = 0;
    for (int c0 = 0; c0 < 512; c0 += 128) {
        __syncthreads();
        for (int i = t; i < 128 * 64; i += 128) es[i] = emb[c0 * 64 + i];
        __syncthreads();
        for (int c = 0; c < 128; c++) {
            float d2 = 0.f;
#pragma unroll
            for (int d = 0; d < 64; d++) {
                float df = xv[d] - es[c * 64 + d];
                d2 += df * df;
            }
            if (d2 < best) { best = d2; bidx = c0 + c; }
        }
    }
    const float* e = emb + (size_t)bidx * 64;
    float* q = zq + (size_t)n * 65536 + hw;
#pragma unroll
    for (int d = 0; d < 64; d++) q[(size_t)d * 1024] = e[d];

    red[t] = best;
    __syncthreads();
    for (int s = 64; s > 0; s >>= 1) {
        if (t < s) red[t] += red[t + s];
        __syncthreads();
    }
    if (t == 0) partial[blockIdx.x] = red[0];
}

__global__ void vq_loss_kernel(const float* __restrict__ partial,
                               float* __restrict__ out_loss) {
    __shared__ float red[256];
    int t = threadIdx.x;
    red[t] = partial[t];
    __syncthreads();
    for (int s = 128; s > 0; s >>= 1) {
        if (t < s) red[t] += red[t + s];
        __syncthreads();
    }
    if (t == 0) out_loss[0] = red[0] * (2.0f / 2097152.0f);
}

// ------------------------------------------------------------------
// convT3 v2: smem-tiled. Block = (yq, n), computes all 4 parities of
// output rows {2yq, 2yq+1}. smem: ws[6144] + dat[3 rows][32 ch][128].
// ------------------------------------------------------------------
__global__ __launch_bounds__(256) void convt3_v2(
    const float* __restrict__ in, const float* __restrict__ w,
    const float* __restrict__ b, float* __restrict__ out) {
    extern __shared__ float s[];
    float* ws = s;             // 6144
    float* dat = s + 6144;     // 3*32*128 = 12288
    const int t = threadIdx.x;
    const int yq = blockIdx.y;
    const int n = blockIdx.z;
    for (int i = t; i < 6144; i += 256) ws[i] = w[i];

    const int py = t >> 7;     // 0..1
    const int xq = t & 127;
    float acc0[3], acc1[3];    // px=0 / px=1
#pragma unroll
    for (int ch = 0; ch < 3; ch++) { acc0[ch] = b[ch]; acc1[ch] = b[ch]; }

    const float* xn = in + (size_t)n * 2097152;
    for (int c0 = 0; c0 < 128; c0 += 32) {
        __syncthreads();
        for (int i = t; i < 12288; i += 256) {
            int r = i >> 12;
            int cc = (i >> 7) & 31;
            int wv = i & 127;
            int h = yq - 1 + r;
            dat[i] = ((unsigned)h < 128u)
                         ? xn[(size_t)(c0 + cc) * 16384 + h * 128 + wv] : 0.f;
        }
        __syncthreads();
        for (int cc = 0; cc < 32; cc++) {
            const float* wsc = ws + (c0 + cc) * 48;
#pragma unroll
            for (int dh = 0; dh < 2; dh++) {
                const int r = py + 1 - dh;      // smem row for h = yq+py-dh
                const float* dr = dat + (r << 12) + (cc << 7);
                float v0 = dr[xq];
                float vm = (xq > 0) ? dr[xq - 1] : 0.f;
                float vp = (xq < 127) ? dr[xq + 1] : 0.f;
                const int kh = 2 * dh + 1 - py;
#pragma unroll
                for (int ch = 0; ch < 3; ch++) {
                    const float* wk = wsc + ch * 16 + kh * 4;
                    acc0[ch] += v0 * wk[1] + vm * wk[3];
                    acc1[ch] += vp * wk[0] + v0 * wk[2];
                }
            }
        }
    }
    const int y = 2 * yq + py;
#pragma unroll
    for (int ch = 0; ch < 3; ch++) {
        float2 q;
        q.x = 1.f / (1.f + expf(-acc0[ch]));
        q.y = 1.f / (1.f + expf(-acc1[ch]));
        *(float2*)&out[(((size_t)n * 3 + ch) << 16) + y * 256 + 2 * xq] = q;
    }
}

// ------------------------------------------------------------------
// Launch
// ------------------------------------------------------------------
extern "C" void kernel_launch(void* const* d_in, const int* in_sizes, int n_in,
                              void* d_out, int out_size) {
    (void)in_sizes; (void)n_in; (void)out_size;
    const float* x   = (const float*)d_in[0];
    const float* ew1 = (const float*)d_in[1];
    const float* eb1 = (const float*)d_in[2];
    const float* ew2 = (const float*)d_in[3];
    const float* eb2 = (const float*)d_in[4];
    const float* ew3 = (const float*)d_in[5];
    const float* eb3 = (const float*)d_in[6];
    const float* pw  = (const float*)d_in[7];
    const float* pb  = (const float*)d_in[8];
    const float* emb = (const float*)d_in[9];
    const float* dw1 = (const float*)d_in[10];
    const float* db1 = (const float*)d_in[11];
    const float* dw2 = (const float*)d_in[12];
    const float* db2 = (const float*)d_in[13];
    const float* dw3 = (const float*)d_in[14];
    const float* db3 = (const float*)d_in[15];
    float* out = (float*)d_out;

    float *arena, *wtp, *part;
    float *w1hi, *w1lo, *w2hi, *w2lo, *w3hi, *w3lo, *wd1hi, *wd2hi;
    cudaGetSymbolAddress((void**)&arena, g_arena);
    cudaGetSymbolAddress((void**)&wtp, g_wtp);
    cudaGetSymbolAddress((void**)&w1hi, g_w1hi);
    cudaGetSymbolAddress((void**)&w1lo, g_w1lo);
    cudaGetSymbolAddress((void**)&w2hi, g_w2hi);
    cudaGetSymbolAddress((void**)&w2lo, g_w2lo);
    cudaGetSymbolAddress((void**)&w3hi, g_w3hi);
    cudaGetSymbolAddress((void**)&w3lo, g_w3lo);
    cudaGetSymbolAddress((void**)&wd1hi, g_wd1hi);
    cudaGetSymbolAddress((void**)&wd2hi, g_wd2hi);
    cudaGetSymbolAddress((void**)&part, g_vqpart);

    float* h1  = arena;
    float* d2b = arena;
    float* h2  = arena + 67108864;
    float* d1b = arena + 67108864;
    float* h3  = arena + 100663296;
    float* ze  = arena + 117440512;
    float* zq  = arena + 119537664;

    // smem sizes: SPLITS3 stage = 2*128*20 + 2*16*136 = 9472 fl; x2 = 75776B
    //             SPLITS1 stage =   128*20 +   16*136 = 4736 fl; x2 = 37888B
    const int SM3 = 2 * 9472 * 4;
    const int SM1 = 2 * 4736 * 4;
    const int SMT3 = (6144 + 12288) * 4;
    cudaFuncSetAttribute(mma_igemm<0, 3, 1>,
                         cudaFuncAttributeMaxDynamicSharedMemorySize, SM3);
    cudaFuncSetAttribute(mma_igemm<2, 1, 1>,
                         cudaFuncAttributeMaxDynamicSharedMemorySize, SM1);
    cudaFuncSetAttribute(convt3_v2,
                         cudaFuncAttributeMaxDynamicSharedMemorySize, SMT3);

    // 3 transform launches (so ncu -s 5 lands on conv3 below)
    xform_misc<<<(825344 + 255) / 256, 256>>>(ew1, w1hi, w1lo, pw, wtp,
                                              dw1, wd1hi, dw2, wd2hi);
    split_tf32_k<<<2048, 256>>>(ew2, w2hi, w2lo, 524288);
    split_tf32_k<<<8192, 256>>>(ew3, w3hi, w3lo, 2097152);

    MP m;
    m.py = 0; m.px = 0;

    // conv1 (3xTF32): x[32,3,256,256] -> h1[32,128,128,128]
    m.x = x; m.whi = w1hi; m.wlo = w1lo; m.bias = eb1; m.out = h1;
    m.Cin = 3; m.Hin = 256; m.Win = 256; m.Mtot = 128;
    m.Hout = 128; m.Wout = 128; m.K = 48; m.sHWo = 14; m.sW = 7;
    mma_igemm<0, 3, 1><<<dim3(4096, 1), 256, SM3>>>(m);

    // conv2 (3xTF32): h1 -> h2[32,256,64,64]
    m.x = h1; m.whi = w2hi; m.wlo = w2lo; m.bias = eb2; m.out = h2;
    m.Cin = 128; m.Hin = 128; m.Win = 128; m.Mtot = 256;
    m.Hout = 64; m.Wout = 64; m.K = 2048; m.sHWo = 12; m.sW = 6;
    mma_igemm<0, 3, 1><<<dim3(1024, 2), 256, SM3>>>(m);

    // conv3 (3xTF32): h2 -> h3[32,512,32,32]   <-- ncu launch idx 5
    m.x = h2; m.whi = w3hi; m.wlo = w3lo; m.bias = eb3; m.out = h3;
    m.Cin = 256; m.Hin = 64; m.Win = 64; m.Mtot = 512;
    m.Hout = 32; m.Wout = 32; m.K = 4096; m.sHWo = 10; m.sW = 5;
    mma_igemm<0, 3, 1><<<dim3(256, 4), 256, SM3>>>(m);

    // pre-VQ 1x1 (SIMT fp32): h3 -> ze
    GP g;
    g.x = h3; g.wt = wtp; g.bias = pb; g.out = ze;
    g.Cin = 512; g.Hin = 1; g.Win = 1024; g.M = 64;
    g.K = 512; g.sHWo = 10; g.sW = 0;
    igemm1x1<0><<<dim3(32768 / 64, 1), 256>>>(g);

    // VQ
    vq_kernel<<<256, 128>>>(ze, emb, zq, part);
    vq_loss_kernel<<<1, 256>>>(part, out + 6291456);

    // convT1 (1xTF32): zq -> d1[32,256,64,64]
    for (int par = 0; par < 4; par++) {
        m.x = zq; m.whi = wd1hi + (size_t)par * 65536; m.wlo = wd1hi;
        m.bias = db1; m.out = d1b;
        m.Cin = 64; m.Hin = 32; m.Win = 32; m.Mtot = 256;
        m.Hout = 64; m.Wout = 64; m.K = 256; m.sHWo = 10; m.sW = 5;
        m.py = par >> 1; m.px = par & 1;
        mma_igemm<2, 1, 1><<<dim3(256, 2), 256, SM1>>>(m);
    }

    // convT2 (1xTF32): d1 -> d2[32,128,128,128]
    for (int par = 0; par < 4; par++) {
        m.x = d1b; m.whi = wd2hi + (size_t)par * 131072; m.wlo = wd2hi;
        m.bias = db2; m.out = d2b;
        m.Cin = 256; m.Hin = 64; m.Win = 64; m.Mtot = 128;
        m.Hout = 128; m.Wout = 128; m.K = 1024; m.sHWo = 12; m.sW = 6;
        m.py = par >> 1; m.px = par & 1;
        mma_igemm<2, 1, 1><<<dim3(1024, 1), 256, SM1>>>(m);
    }

    // convT3 v2 (smem-tiled) + sigmoid
    convt3_v2<<<dim3(1, 128, 32), 256, SMT3>>>(d2b, dw3, db3, out);
}

// round 8
// speedup vs baseline: 1.7079x; 1.1078x over previous
#include <cuda_runtime.h>
#include <math.h>
#include <stdint.h>

// ------------------------------------------------------------------
// Scratch (device globals). Arena lifetime-aliased: h1/d2, h2/d1.
// ------------------------------------------------------------------
__device__ float g_arena[121634816];
__device__ float g_wtp[32768];       // 1x1 SIMT [k][m]
__device__ float g_w1hi[6144];       // conv1  packed frag-major hi/lo
__device__ float g_w1lo[6144];
__device__ float g_w2hi[524288];     // conv2 packed
__device__ float g_w2lo[524288];
__device__ float g_w3hi[2097152];    // conv3 packed
__device__ float g_w3lo[2097152];
__device__ float g_wd1hi[262144];    // convT1 [par] packed (hi only)
__device__ float g_wd2hi[524288];    // convT2 [par] packed (hi only)
__device__ float g_vqe2[512];
__device__ float g_vqpart[256];

// ------------------------------------------------------------------
// Helpers
// ------------------------------------------------------------------
__device__ __forceinline__ float tf32r(float v) {
    uint32_t u;
    asm("cvt.rna.tf32.f32 %0, %1;" : "=r"(u) : "f"(v));
    return __uint_as_float(u);
}
__device__ __forceinline__ uint32_t smem_u32(const void* p) {
    uint32_t a;
    asm("{ .reg .u64 t; cvta.to.shared.u64 t, %1; cvt.u32.u64 %0, t; }"
        : "=r"(a) : "l"(p));
    return a;
}
__device__ __forceinline__ void cpasync16(uint32_t dst, const void* src) {
    asm volatile("cp.async.cg.shared.global [%0], [%1], 16;"
                 :: "r"(dst), "l"(src));
}
#define CP_COMMIT() asm volatile("cp.async.commit_group;" ::: "memory")
#define CP_WAIT0()  asm volatile("cp.async.wait_group 0;" ::: "memory")

__device__ __forceinline__ void mma8(float* d, const float* a, const float* b) {
    asm volatile(
        "mma.sync.aligned.m16n8k8.row.col.f32.tf32.tf32.f32 "
        "{%0,%1,%2,%3},{%4,%5,%6,%7},{%8,%9},{%0,%1,%2,%3};"
        : "+f"(d[0]), "+f"(d[1]), "+f"(d[2]), "+f"(d[3])
        : "r"(__float_as_uint(a[0])), "r"(__float_as_uint(a[1])),
          "r"(__float_as_uint(a[2])), "r"(__float_as_uint(a[3])),
          "r"(__float_as_uint(b[0])), "r"(__float_as_uint(b[1])));
}

// fragment-major pack offset within a (128m x 16k) block of A.
// consumer: thread lane=(gp*4+tg) of warp with wmh reads float4 at
// index ((wmh*2+ks)*4+mi)*32 + lane  -> j=0..3 = mma a[0..3]
__device__ __forceinline__ int packoff(int mr, int kk) {
    int wmh = mr >> 6, mi = (mr >> 4) & 3, r8 = (mr >> 3) & 1, gp = mr & 7;
    int ks = kk >> 3, j2 = (kk >> 2) & 1, tg = kk & 3;
    return ((((wmh * 2 + ks) * 4 + mi) * 32) + gp * 4 + tg) * 4 + (r8 + 2 * j2);
}

// ------------------------------------------------------------------
// Weight transforms (2 launches total)
// ------------------------------------------------------------------
// L1: w1 pack (6144) | pw fwd (32768) | convT1 pack (262144) |
//     convT2 pack (524288) | emb e2 (512)
__global__ void xform_misc(const float* __restrict__ ew1, float* __restrict__ w1hi,
                           float* __restrict__ w1lo,
                           const float* __restrict__ pw, float* __restrict__ wtp,
                           const float* __restrict__ dw1, float* __restrict__ wd1hi,
                           const float* __restrict__ dw2, float* __restrict__ wd2hi,
                           const float* __restrict__ emb, float* __restrict__ e2) {
    int idx = blockIdx.x * 256 + threadIdx.x;
    if (idx < 6144) {                       // conv1: Cout=128, K=48
        int m = idx / 48, k = idx - m * 48;
        float v = ew1[idx];
        float h = tf32r(v);
        int dest = (k >> 4) * 2048 + packoff(m & 127, k & 15);
        w1hi[dest] = h;
        w1lo[dest] = tf32r(v - h);
    } else if (idx < 38912) {               // 1x1: Cout=64, CK=512
        int i = idx - 6144;
        int co = i / 512, k = i - co * 512;
        wtp[k * 64 + co] = pw[i];
    } else if (idx < 301056) {              // convT1: Cin=64, Cout=256, K=256
        int i = idx - 38912;
        int par = i >> 16, rem = i & 65535;
        int o = rem >> 8, kidx = rem & 255;
        int ci = kidx >> 2, dh = (kidx >> 1) & 1, dw = kidx & 1;
        int py = par >> 1, px = par & 1;
        int kh = 2 * dh + 1 - py, kw = 2 * dw + 1 - px;
        float v = dw1[((ci * 256 + o) * 4 + kh) * 4 + kw];
        int dest = par * 65536 + ((o >> 7) * 16 + (kidx >> 4)) * 2048 +
                   packoff(o & 127, kidx & 15);
        wd1hi[dest] = tf32r(v);
    } else if (idx < 825344) {              // convT2: Cin=256, Cout=128, K=1024
        int i = idx - 301056;
        int par = i >> 17, rem = i & 131071;
        int o = rem >> 10, kidx = rem & 1023;
        int ci = kidx >> 2, dh = (kidx >> 1) & 1, dw = kidx & 1;
        int py = par >> 1, px = par & 1;
        int kh = 2 * dh + 1 - py, kw = 2 * dw + 1 - px;
        float v = dw2[((ci * 128 + o) * 4 + kh) * 4 + kw];
        int dest = par * 131072 + (kidx >> 4) * 2048 + packoff(o, kidx & 15);
        wd2hi[dest] = tf32r(v);
    } else if (idx < 825856) {              // e2
        int c = idx - 825344;
        float s = 0.f;
        for (int d = 0; d < 64; d++) {
            float e = emb[c * 64 + d];
            s += e * e;
        }
        e2[c] = s;
    }
}

// L2: conv2 (524288, K=2048, Cout=256) + conv3 (2097152, K=4096, Cout=512)
__global__ void pack_fwd(const float* __restrict__ ew2, float* __restrict__ w2hi,
                         float* __restrict__ w2lo,
                         const float* __restrict__ ew3, float* __restrict__ w3hi,
                         float* __restrict__ w3lo) {
    int idx = blockIdx.x * 256 + threadIdx.x;
    if (idx < 524288) {
        int m = idx >> 11, k = idx & 2047;
        float v = ew2[idx];
        float h = tf32r(v);
        int dest = ((m >> 7) * 128 + (k >> 4)) * 2048 + packoff(m & 127, k & 15);
        w2hi[dest] = h;
        w2lo[dest] = tf32r(v - h);
    } else if (idx < 524288 + 2097152) {
        int i = idx - 524288;
        int m = i >> 12, k = i & 4095;
        float v = ew3[i];
        float h = tf32r(v);
        int dest = ((m >> 7) * 256 + (k >> 4)) * 2048 + packoff(m & 127, k & 15);
        w3hi[dest] = h;
        w3lo[dest] = tf32r(v - h);
    }
}

// ------------------------------------------------------------------
// Warp-MMA tf32 implicit GEMM: C[m][p] = sum_k W[m][k]*X[p][k]
// BM=128, BN=128, BK=16; 8 warps (2x4), warp tile 64x32.
// A: fragment-major packed gmem -> cp.async -> LDS.128 per fragment.
// B: LDG gather -> reg convert -> STS [k][p] (LDB=136).
// MODE 0: stride-2 4x4 conv; MODE 2: convT parity (par = blockIdx.z).
// ------------------------------------------------------------------
struct MP {
    const float* x;
    const float* whi;
    const float* wlo;
    const float* bias;
    float* out;
    int Cin, Hin, Win, Mtot, Hout, Wout, K, sHWo, sW;
};

template <int MODE, int SPLITS, int ACT>
__global__ __launch_bounds__(256, 2) void mma_igemm(MP g) {
    extern __shared__ __align__(16) float sm[];
    constexpr int LDB = 136;
    constexpr int AHI = 0;
    constexpr int ALO = 2048;
    constexpr int BHI = (SPLITS == 3) ? 4096 : 2048;
    constexpr int BLO = BHI + 16 * LDB;
    constexpr int STAGE = BHI + (SPLITS == 3 ? 2 : 1) * 16 * LDB;

    const int t = threadIdx.x;
    const int lane = t & 31;
    const int wid = t >> 5;
    const int p0 = blockIdx.x * 128;
    const int m0 = blockIdx.y * 128;
    const int par = (MODE == 2) ? blockIdx.z : 0;
    const int py = par >> 1, px = par & 1;
    const uint32_t sbase = smem_u32(sm);
    const float* __restrict__ whiP =
        g.whi + (size_t)par * g.Mtot * g.K +
        ((size_t)(m0 >> 7) * (g.K >> 4)) * 2048;
    const float* __restrict__ wloP =
        (SPLITS == 3)
            ? g.wlo + ((size_t)(m0 >> 7) * (g.K >> 4)) * 2048
            : whiP;

    // B loader role
    const int lm = t & 127;
    const int kq = (t >> 7) * 8;

    // im2col decode for p = p0 + lm
    const int p = p0 + lm;
    const int n = p >> g.sHWo;
    const int rem = p & ((1 << g.sHWo) - 1);
    const int ho = rem >> g.sW, wo = rem & ((1 << g.sW) - 1);
    const float* __restrict__ xn = g.x + (size_t)n * g.Cin * g.Hin * g.Win;
    const int HW = g.Hin * g.Win;

    int rowoff[4], iwv[4];
    bool okh[4], okw[4];
    if (MODE == 0) {
#pragma unroll
        for (int kh = 0; kh < 4; kh++) {
            int ih = 2 * ho - 1 + kh;
            okh[kh] = (unsigned)ih < (unsigned)g.Hin;
            rowoff[kh] = ih * g.Win;
        }
#pragma unroll
        for (int kw = 0; kw < 4; kw++) {
            int iw = 2 * wo - 1 + kw;
            okw[kw] = (unsigned)iw < (unsigned)g.Win;
            iwv[kw] = iw;
        }
    } else {
#pragma unroll
        for (int dh = 0; dh < 2; dh++) {
            int ih = ho + py - dh;
            okh[dh] = (unsigned)ih < (unsigned)g.Hin;
            rowoff[dh] = ih * g.Win;
        }
#pragma unroll
        for (int dw = 0; dw < 2; dw++) {
            int iw = wo + px - dw;
            okw[dw] = (unsigned)iw < (unsigned)g.Win;
            iwv[dw] = iw;
        }
    }

    const int wmh = wid >> 2;         // warp m-half (0/1)
    const int wn = (wid & 3) * 32;
    const int gp = lane >> 2;
    const int tg = lane & 3;

    float acc[4][4][4];
#pragma unroll
    for (int mi = 0; mi < 4; mi++)
#pragma unroll
        for (int ni = 0; ni < 4; ni++)
#pragma unroll
            for (int r = 0; r < 4; r++) acc[mi][ni][r] = 0.f;

    float bh[8], blr[8];

    auto issueA = [&](int c, int s) {
        uint32_t d = sbase + (uint32_t)(s * STAGE + AHI + t * 8) * 4;
        const float* srcH = whiP + (size_t)c * 2048 + t * 8;
        cpasync16(d, srcH);
        cpasync16(d + 16, srcH + 4);
        if (SPLITS == 3) {
            uint32_t d2 = sbase + (uint32_t)(s * STAGE + ALO + t * 8) * 4;
            const float* srcL = wloP + (size_t)c * 2048 + t * 8;
            cpasync16(d2, srcL);
            cpasync16(d2 + 16, srcL + 4);
        }
    };

    auto gatherB = [&](int c) {
        if (MODE == 0) {
            const float* bp = xn + (size_t)c * HW;
#pragma unroll
            for (int j = 0; j < 8; j++) {
                int tap = kq + j;
                int kh = tap >> 2, kw = tap & 3;
                float v = (okh[kh] && okw[kw]) ? bp[rowoff[kh] + iwv[kw]] : 0.f;
                float h = tf32r(v);
                bh[j] = h;
                if (SPLITS == 3) blr[j] = tf32r(v - h);
            }
        } else {
#pragma unroll
            for (int j = 0; j < 8; j++) {
                int tap = kq + j;
                int cl = tap >> 2, dd = tap & 3;
                int dh = dd >> 1, dw = dd & 1;
                const float* bp = xn + (size_t)(c * 4 + cl) * HW;
                float v = (okh[dh] && okw[dw]) ? bp[rowoff[dh] + iwv[dw]] : 0.f;
                float h = tf32r(v);
                bh[j] = h;
                if (SPLITS == 3) blr[j] = tf32r(v - h);
            }
        }
    };

    auto stsB = [&](int s) {
        float* S = sm + s * STAGE;
#pragma unroll
        for (int j = 0; j < 8; j++) {
            S[BHI + (kq + j) * LDB + lm] = bh[j];
            if (SPLITS == 3) S[BLO + (kq + j) * LDB + lm] = blr[j];
        }
    };

    auto compute = [&](int s) {
        const float* S = sm + s * STAGE;
        const float4* A4 = (const float4*)(S + AHI);
        const float4* A4l = (const float4*)(S + ALO);
#pragma unroll
        for (int ks = 0; ks < 2; ks++) {
            const int kb = ks * 8;
            float b[4][2], b2[4][2];
#pragma unroll
            for (int ni = 0; ni < 4; ni++) {
                int pc = wn + ni * 8 + gp;
                b[ni][0] = S[BHI + (kb + tg) * LDB + pc];
                b[ni][1] = S[BHI + (kb + tg + 4) * LDB + pc];
                if (SPLITS == 3) {
                    b2[ni][0] = S[BLO + (kb + tg) * LDB + pc];
                    b2[ni][1] = S[BLO + (kb + tg + 4) * LDB + pc];
                }
            }
#pragma unroll
            for (int mi = 0; mi < 4; mi++) {
                const int fidx = ((wmh * 2 + ks) * 4 + mi) * 32 + lane;
                float4 af = A4[fidx];
                float a[4] = {af.x, af.y, af.z, af.w};
#pragma unroll
                for (int ni = 0; ni < 4; ni++) mma8(acc[mi][ni], a, b[ni]);
                if (SPLITS == 3) {
                    float4 af2 = A4l[fidx];
                    float a2[4] = {af2.x, af2.y, af2.z, af2.w};
#pragma unroll
                    for (int ni = 0; ni < 4; ni++) mma8(acc[mi][ni], a2, b[ni]);
#pragma unroll
                    for (int ni = 0; ni < 4; ni++) mma8(acc[mi][ni], a, b2[ni]);
                }
            }
        }
    };

    const int nc = g.K >> 4;
    issueA(0, 0);
    CP_COMMIT();
    gatherB(0);
    stsB(0);
    CP_WAIT0();
    __syncthreads();
    for (int c = 0; c < nc; c++) {
        const int s = c & 1;
        if (c + 1 < nc) {
            issueA(c + 1, s ^ 1);
            CP_COMMIT();
            gatherB(c + 1);
        }
        compute(s);
        if (c + 1 < nc) {
            stsB(s ^ 1);
            CP_WAIT0();
        }
        __syncthreads();
    }

    // epilogue
    const int HWo = 1 << g.sHWo;
    const int nn = p0 >> g.sHWo;
    const int rem0 = p0 & (HWo - 1);
#pragma unroll
    for (int mi = 0; mi < 4; mi++) {
        const int mA = m0 + wmh * 64 + mi * 16 + gp;
        const int mB = mA + 8;
        const float bA = g.bias[mA];
        const float bB = g.bias[mB];
#pragma unroll
        for (int ni = 0; ni < 4; ni++) {
            const int col = wn + ni * 8 + 2 * tg;
            float v0 = acc[mi][ni][0] + bA;
            float v1 = acc[mi][ni][1] + bA;
            float v2 = acc[mi][ni][2] + bB;
            float v3 = acc[mi][ni][3] + bB;
            if (ACT) {
                v0 = fmaxf(v0, 0.f); v1 = fmaxf(v1, 0.f);
                v2 = fmaxf(v2, 0.f); v3 = fmaxf(v3, 0.f);
            }
            if (MODE == 0) {
                float2 q0 = {v0, v1}, q1 = {v2, v3};
                *(float2*)&g.out[((size_t)nn * g.Mtot + mA) * HWo + rem0 + col] = q0;
                *(float2*)&g.out[((size_t)nn * g.Mtot + mB) * HWo + rem0 + col] = q1;
            } else {
                int rr = rem0 + col;
                int hh = rr >> g.sW, ww = rr & ((1 << g.sW) - 1);
                size_t r0 = ((size_t)nn * g.Mtot + mA) * g.Hout + 2 * hh + py;
                g.out[r0 * g.Wout + 2 * ww + px] = v0;
                g.out[r0 * g.Wout + 2 * (ww + 1) + px] = v1;
                size_t r1 = ((size_t)nn * g.Mtot + mB) * g.Hout + 2 * hh + py;
                g.out[r1 * g.Wout + 2 * ww + px] = v2;
                g.out[r1 * g.Wout + 2 * (ww + 1) + px] = v3;
            }
        }
    }
}

// ------------------------------------------------------------------
// SIMT implicit GEMM (1x1 conv only)
// ------------------------------------------------------------------
struct GP {
    const float* x;
    const float* wt;
    const float* bias;
    float* out;
    int Cin, Hin, Win, M, K, sHWo, sW;
};

template <int ACT>
__global__ __launch_bounds__(256) void igemm1x1(GP g) {
    __shared__ __align__(16) float As[16][64];
    __shared__ __align__(16) float Bs[16][64];
    const int t = threadIdx.x;
    const int p0 = blockIdx.x * 64;
    const int m0 = blockIdx.y * 64;
    const int lc = t & 63, lr = t >> 6;
    const int tx = t & 15, ty = t >> 4;

    const int pB = p0 + lc;
    const int nB = pB >> g.sHWo;
    const int remB = pB & ((1 << g.sHWo) - 1);
    const float* __restrict__ xn = g.x + (size_t)nB * g.Cin * g.Hin * g.Win;

    float acc[4][4];
#pragma unroll
    for (int i = 0; i < 4; i++)
#pragma unroll
        for (int j = 0; j < 4; j++) acc[i][j] = 0.f;

    for (int k0 = 0; k0 < g.K; k0 += 16) {
#pragma unroll
        for (int j = 0; j < 4; j++) {
            int r = lr + 4 * j;
            As[r][lc] = g.wt[(size_t)(k0 + r) * g.M + m0 + lc];
            Bs[r][lc] = xn[(size_t)(k0 + r) * g.Win + remB];
        }
        __syncthreads();
#pragma unroll
        for (int kk = 0; kk < 16; kk++) {
            float4 a4 = *(const float4*)&As[kk][ty * 4];
            float4 b4 = *(const float4*)&Bs[kk][tx * 4];
            float av[4] = {a4.x, a4.y, a4.z, a4.w};
            float bv[4] = {b4.x, b4.y, b4.z, b4.w};
#pragma unroll
            for (int i = 0; i < 4; i++)
#pragma unroll
                for (int j = 0; j < 4; j++) acc[i][j] += av[i] * bv[j];
        }
        __syncthreads();
    }

    const int HWo = 1 << g.sHWo;
#pragma unroll
    for (int j = 0; j < 4; j++) {
        int p = p0 + tx * 4 + j;
        int nn = p >> g.sHWo;
        int rm = p & (HWo - 1);
#pragma unroll
        for (int i = 0; i < 4; i++) {
            int m = m0 + ty * 4 + i;
            float v = acc[i][j] + g.bias[m];
            if (ACT == 1) v = fmaxf(v, 0.f);
            g.out[((size_t)nn * g.M + m) * HWo + rm] = v;
        }
    }
}

// ------------------------------------------------------------------
// VQ v2 (dot-product form, float4 broadcast) + loss
// score = e2[c] - 2*dot(x, e); dist = x2 + score (matches ref formula)
// ------------------------------------------------------------------
__global__ __launch_bounds__(128) void vq_kernel(
    const float* __restrict__ ze, const float* __restrict__ emb,
    const float* __restrict__ e2, float* __restrict__ zq,
    float* __restrict__ partial) {
    __shared__ float es[8192];
    __shared__ float e2s[128];
    __shared__ float red[128];
    const int t = threadIdx.x;
    const int pos = blockIdx.x * 128 + t;
    const int n = pos >> 10;
    const int hw = pos & 1023;

    float xv[64];
    const float* zp = ze + (size_t)n * 65536 + hw;
    float x2 = 0.f;
#pragma unroll
    for (int d = 0; d < 64; d++) {
        xv[d] = zp[(size_t)d * 1024];
        x2 += xv[d] * xv[d];
    }

    float best = 3.0e38f;
    int bidx = 0;
    for (int c0 = 0; c0 < 512; c0 += 128) {
        __syncthreads();
        {
            const float4* src = (const float4*)(emb + c0 * 64);
            float4* dst = (float4*)es;
            for (int i = t; i < 2048; i += 128) dst[i] = src[i];
            e2s[t] = e2[c0 + t];
        }
        __syncthreads();
        for (int c = 0; c < 128; c++) {
            float dot = 0.f;
            const float4* ep = (const float4*)(es + c * 64);
#pragma unroll
            for (int q = 0; q < 16; q++) {
                float4 e4 = ep[q];
                dot += xv[q * 4] * e4.x + xv[q * 4 + 1] * e4.y +
                       xv[q * 4 + 2] * e4.z + xv[q * 4 + 3] * e4.w;
            }
            float sc = e2s[c] - 2.f * dot;
            if (sc < best) { best = sc; bidx = c0 + c; }
        }
    }
    const float* e = emb + (size_t)bidx * 64;
    float* q = zq + (size_t)n * 65536 + hw;
#pragma unroll
    for (int d = 0; d < 64; d++) q[(size_t)d * 1024] = e[d];

    red[t] = x2 + best;
    __syncthreads();
    for (int s = 64; s > 0; s >>= 1) {
        if (t < s) red[t] += red[t + s];
        __syncthreads();
    }
    if (t == 0) partial[blockIdx.x] = red[0];
}

__global__ void vq_loss_kernel(const float* __restrict__ partial,
                               float* __restrict__ out_loss) {
    __shared__ float red[256];
    int t = threadIdx.x;
    red[t] = partial[t];
    __syncthreads();
    for (int s = 128; s > 0; s >>= 1) {
        if (t < s) red[t] += red[t + s];
        __syncthreads();
    }
    if (t == 0) out_loss[0] = red[0] * (2.0f / 2097152.0f);
}

// ------------------------------------------------------------------
// convT3 v2: smem-tiled direct + sigmoid
// ------------------------------------------------------------------
__global__ __launch_bounds__(256) void convt3_v2(
    const float* __restrict__ in, const float* __restrict__ w,
    const float* __restrict__ b, float* __restrict__ out) {
    extern __shared__ float s[];
    float* ws = s;             // 6144
    float* dat = s + 6144;     // 3*32*128 = 12288
    const int t = threadIdx.x;
    const int yq = blockIdx.y;
    const int n = blockIdx.z;
    for (int i = t; i < 6144; i += 256) ws[i] = w[i];

    const int py = t >> 7;
    const int xq = t & 127;
    float acc0[3], acc1[3];
#pragma unroll
    for (int ch = 0; ch < 3; ch++) { acc0[ch] = b[ch]; acc1[ch] = b[ch]; }

    const float* xn = in + (size_t)n * 2097152;
    for (int c0 = 0; c0 < 128; c0 += 32) {
        __syncthreads();
        for (int i = t; i < 12288; i += 256) {
            int r = i >> 12;
            int cc = (i >> 7) & 31;
            int wv = i & 127;
            int h = yq - 1 + r;
            dat[i] = ((unsigned)h < 128u)
                         ? xn[(size_t)(c0 + cc) * 16384 + h * 128 + wv] : 0.f;
        }
        __syncthreads();
        for (int cc = 0; cc < 32; cc++) {
            const float* wsc = ws + (c0 + cc) * 48;
#pragma unroll
            for (int dh = 0; dh < 2; dh++) {
                const int r = py + 1 - dh;
                const float* dr = dat + (r << 12) + (cc << 7);
                float v0 = dr[xq];
                float vm = (xq > 0) ? dr[xq - 1] : 0.f;
                float vp = (xq < 127) ? dr[xq + 1] : 0.f;
                const int kh = 2 * dh + 1 - py;
#pragma unroll
                for (int ch = 0; ch < 3; ch++) {
                    const float* wk = wsc + ch * 16 + kh * 4;
                    acc0[ch] += v0 * wk[1] + vm * wk[3];
                    acc1[ch] += vp * wk[0] + v0 * wk[2];
                }
            }
        }
    }
    const int y = 2 * yq + py;
#pragma unroll
    for (int ch = 0; ch < 3; ch++) {
        float2 q;
        q.x = 1.f / (1.f + expf(-acc0[ch]));
        q.y = 1.f / (1.f + expf(-acc1[ch]));
        *(float2*)&out[(((size_t)n * 3 + ch) << 16) + y * 256 + 2 * xq] = q;
    }
}

// ------------------------------------------------------------------
// Launch
// ------------------------------------------------------------------
extern "C" void kernel_launch(void* const* d_in, const int* in_sizes, int n_in,
                              void* d_out, int out_size) {
    (void)in_sizes; (void)n_in; (void)out_size;
    const float* x   = (const float*)d_in[0];
    const float* ew1 = (const float*)d_in[1];
    const float* eb1 = (const float*)d_in[2];
    const float* ew2 = (const float*)d_in[3];
    const float* eb2 = (const float*)d_in[4];
    const float* ew3 = (const float*)d_in[5];
    const float* eb3 = (const float*)d_in[6];
    const float* pw  = (const float*)d_in[7];
    const float* pb  = (const float*)d_in[8];
    const float* emb = (const float*)d_in[9];
    const float* dw1 = (const float*)d_in[10];
    const float* db1 = (const float*)d_in[11];
    const float* dw2 = (const float*)d_in[12];
    const float* db2 = (const float*)d_in[13];
    const float* dw3 = (const float*)d_in[14];
    const float* db3 = (const float*)d_in[15];
    float* out = (float*)d_out;

    float *arena, *wtp, *part, *e2;
    float *w1hi, *w1lo, *w2hi, *w2lo, *w3hi, *w3lo, *wd1hi, *wd2hi;
    cudaGetSymbolAddress((void**)&arena, g_arena);
    cudaGetSymbolAddress((void**)&wtp, g_wtp);
    cudaGetSymbolAddress((void**)&w1hi, g_w1hi);
    cudaGetSymbolAddress((void**)&w1lo, g_w1lo);
    cudaGetSymbolAddress((void**)&w2hi, g_w2hi);
    cudaGetSymbolAddress((void**)&w2lo, g_w2lo);
    cudaGetSymbolAddress((void**)&w3hi, g_w3hi);
    cudaGetSymbolAddress((void**)&w3lo, g_w3lo);
    cudaGetSymbolAddress((void**)&wd1hi, g_wd1hi);
    cudaGetSymbolAddress((void**)&wd2hi, g_wd2hi);
    cudaGetSymbolAddress((void**)&e2, g_vqe2);
    cudaGetSymbolAddress((void**)&part, g_vqpart);

    float* h1  = arena;
    float* d2b = arena;
    float* h2  = arena + 67108864;
    float* d1b = arena + 67108864;
    float* h3  = arena + 100663296;
    float* ze  = arena + 117440512;
    float* zq  = arena + 119537664;

    // smem: S3 stage = 4096 + 2*2176 = 8448 fl; x2 = 67584 B
    //       S1 stage = 2048 + 2176   = 4224 fl; x2 = 33792 B
    const int SM3 = 2 * 8448 * 4;
    const int SM1 = 2 * 4224 * 4;
    const int SMT3 = (6144 + 12288) * 4;
    cudaFuncSetAttribute(mma_igemm<0, 3, 1>,
                         cudaFuncAttributeMaxDynamicSharedMemorySize, SM3);
    cudaFuncSetAttribute(mma_igemm<2, 1, 1>,
                         cudaFuncAttributeMaxDynamicSharedMemorySize, SM1);
    cudaFuncSetAttribute(convt3_v2,
                         cudaFuncAttributeMaxDynamicSharedMemorySize, SMT3);

    // 2 transform launches (capture slot -> conv2)
    xform_misc<<<(825856 + 255) / 256, 256>>>(ew1, w1hi, w1lo, pw, wtp,
                                              dw1, wd1hi, dw2, wd2hi, emb, e2);
    pack_fwd<<<(2621440 + 255) / 256, 256>>>(ew2, w2hi, w2lo, ew3, w3hi, w3lo);

    MP m;
    // conv1 (3xTF32): x[32,3,256,256] -> h1[32,128,128,128]
    m.x = x; m.whi = w1hi; m.wlo = w1lo; m.bias = eb1; m.out = h1;
    m.Cin = 3; m.Hin = 256; m.Win = 256; m.Mtot = 128;
    m.Hout = 128; m.Wout = 128; m.K = 48; m.sHWo = 14; m.sW = 7;
    mma_igemm<0, 3, 1><<<dim3(4096, 1), 256, SM3>>>(m);

    // conv2 (3xTF32): h1 -> h2[32,256,64,64]
    m.x = h1; m.whi = w2hi; m.wlo = w2lo; m.bias = eb2; m.out = h2;
    m.Cin = 128; m.Hin = 128; m.Win = 128; m.Mtot = 256;
    m.Hout = 64; m.Wout = 64; m.K = 2048; m.sHWo = 12; m.sW = 6;
    mma_igemm<0, 3, 1><<<dim3(1024, 2), 256, SM3>>>(m);

    // conv3 (3xTF32): h2 -> h3[32,512,32,32]
    m.x = h2; m.whi = w3hi; m.wlo = w3lo; m.bias = eb3; m.out = h3;
    m.Cin = 256; m.Hin = 64; m.Win = 64; m.Mtot = 512;
    m.Hout = 32; m.Wout = 32; m.K = 4096; m.sHWo = 10; m.sW = 5;
    mma_igemm<0, 3, 1><<<dim3(256, 4), 256, SM3>>>(m);

    // pre-VQ 1x1 (SIMT fp32): h3 -> ze
    GP g;
    g.x = h3; g.wt = wtp; g.bias = pb; g.out = ze;
    g.Cin = 512; g.Hin = 1; g.Win = 1024; g.M = 64;
    g.K = 512; g.sHWo = 10; g.sW = 0;
    igemm1x1<0><<<dim3(32768 / 64, 1), 256>>>(g);

    // VQ
    vq_kernel<<<256, 128>>>(ze, emb, e2, zq, part);
    vq_loss_kernel<<<1, 256>>>(part, out + 6291456);

    // convT1 (1xTF32): zq -> d1[32,256,64,64]  (4 pars via grid z)
    m.x = zq; m.whi = wd1hi; m.wlo = wd1hi; m.bias = db1; m.out = d1b;
    m.Cin = 64; m.Hin = 32; m.Win = 32; m.Mtot = 256;
    m.Hout = 64; m.Wout = 64; m.K = 256; m.sHWo = 10; m.sW = 5;
    mma_igemm<2, 1, 1><<<dim3(256, 2, 4), 256, SM1>>>(m);

    // convT2 (1xTF32): d1 -> d2[32,128,128,128]  (4 pars via grid z)
    m.x = d1b; m.whi = wd2hi; m.wlo = wd2hi; m.bias = db2; m.out = d2b;
    m.Cin = 256; m.Hin = 64; m.Win = 64; m.Mtot = 128;
    m.Hout = 128; m.Wout = 128; m.K = 1024; m.sHWo = 12; m.sW = 6;
    mma_igemm<2, 1, 1><<<dim3(1024, 1, 4), 256, SM1>>>(m);

    // convT3 v2 (smem-tiled) + sigmoid
    convt3_v2<<<dim3(1, 128, 32), 256, SMT3>>>(d2b, dw3, db3, out);
}

// round 9
// speedup vs baseline: 2.0871x; 1.2220x over previous
#include <cuda_runtime.h>
#include <math.h>
#include <stdint.h>

// ------------------------------------------------------------------
// Scratch (device globals). Arena lifetime-aliased: h1/d2, h2/d1.
// ------------------------------------------------------------------
__device__ float g_arena[121634816];
__device__ float g_wtp[32768];       // 1x1 SIMT [k][m]
__device__ float g_w1hi[6144];       // conv1  packed frag-major hi/lo
__device__ float g_w1lo[6144];
__device__ float g_w2hi[524288];     // conv2 packed
__device__ float g_w2lo[524288];
__device__ float g_w3hi[2097152];    // conv3 packed
__device__ float g_w3lo[2097152];
__device__ float g_wd1hi[262144];    // convT1 [par] packed (hi only)
__device__ float g_wd2hi[524288];    // convT2 [par] packed (hi only)
__device__ float g_vqe2[512];
__device__ float g_vqpart[256];

// ------------------------------------------------------------------
// Helpers
// ------------------------------------------------------------------
__device__ __forceinline__ float tf32r(float v) {
    uint32_t u;
    asm("cvt.rna.tf32.f32 %0, %1;" : "=r"(u) : "f"(v));
    return __uint_as_float(u);
}
__device__ __forceinline__ uint32_t smem_u32(const void* p) {
    uint32_t a;
    asm("{ .reg .u64 t; cvta.to.shared.u64 t, %1; cvt.u32.u64 %0, t; }"
        : "=r"(a) : "l"(p));
    return a;
}
__device__ __forceinline__ void cpasync16(uint32_t dst, const void* src) {
    asm volatile("cp.async.cg.shared.global [%0], [%1], 16;"
                 :: "r"(dst), "l"(src));
}
// 4B cp.async with zero-fill when pred=0 (src not accessed)
__device__ __forceinline__ void cpasync4z(uint32_t dst, const void* src,
                                          uint32_t sz) {
    asm volatile("cp.async.ca.shared.global [%0], [%1], 4, %2;"
                 :: "r"(dst), "l"(src), "r"(sz));
}
#define CP_COMMIT() asm volatile("cp.async.commit_group;" ::: "memory")
#define CP_WAIT1()  asm volatile("cp.async.wait_group 1;" ::: "memory")
#define CP_WAIT0()  asm volatile("cp.async.wait_group 0;" ::: "memory")

__device__ __forceinline__ void mma8(float* d, const float* a, const float* b) {
    asm volatile(
        "mma.sync.aligned.m16n8k8.row.col.f32.tf32.tf32.f32 "
        "{%0,%1,%2,%3},{%4,%5,%6,%7},{%8,%9},{%0,%1,%2,%3};"
        : "+f"(d[0]), "+f"(d[1]), "+f"(d[2]), "+f"(d[3])
        : "r"(__float_as_uint(a[0])), "r"(__float_as_uint(a[1])),
          "r"(__float_as_uint(a[2])), "r"(__float_as_uint(a[3])),
          "r"(__float_as_uint(b[0])), "r"(__float_as_uint(b[1])));
}

// fragment-major pack offset within a (128m x 16k) block of A.
__device__ __forceinline__ int packoff(int mr, int kk) {
    int wmh = mr >> 6, mi = (mr >> 4) & 3, r8 = (mr >> 3) & 1, gp = mr & 7;
    int ks = kk >> 3, j2 = (kk >> 2) & 1, tg = kk & 3;
    return ((((wmh * 2 + ks) * 4 + mi) * 32) + gp * 4 + tg) * 4 + (r8 + 2 * j2);
}

// ------------------------------------------------------------------
// Weight transforms (2 launches total)
// ------------------------------------------------------------------
__global__ void xform_misc(const float* __restrict__ ew1, float* __restrict__ w1hi,
                           float* __restrict__ w1lo,
                           const float* __restrict__ pw, float* __restrict__ wtp,
                           const float* __restrict__ dw1, float* __restrict__ wd1hi,
                           const float* __restrict__ dw2, float* __restrict__ wd2hi,
                           const float* __restrict__ emb, float* __restrict__ e2) {
    int idx = blockIdx.x * 256 + threadIdx.x;
    if (idx < 6144) {                       // conv1: Cout=128, K=48
        int m = idx / 48, k = idx - m * 48;
        float v = ew1[idx];
        float h = tf32r(v);
        int dest = (k >> 4) * 2048 + packoff(m & 127, k & 15);
        w1hi[dest] = h;
        w1lo[dest] = tf32r(v - h);
    } else if (idx < 38912) {               // 1x1: Cout=64, CK=512
        int i = idx - 6144;
        int co = i / 512, k = i - co * 512;
        wtp[k * 64 + co] = pw[i];
    } else if (idx < 301056) {              // convT1: Cin=64, Cout=256, K=256
        int i = idx - 38912;
        int par = i >> 16, rem = i & 65535;
        int o = rem >> 8, kidx = rem & 255;
        int ci = kidx >> 2, dh = (kidx >> 1) & 1, dw = kidx & 1;
        int py = par >> 1, px = par & 1;
        int kh = 2 * dh + 1 - py, kw = 2 * dw + 1 - px;
        float v = dw1[((ci * 256 + o) * 4 + kh) * 4 + kw];
        int dest = par * 65536 + ((o >> 7) * 16 + (kidx >> 4)) * 2048 +
                   packoff(o & 127, kidx & 15);
        wd1hi[dest] = tf32r(v);
    } else if (idx < 825344) {              // convT2: Cin=256, Cout=128, K=1024
        int i = idx - 301056;
        int par = i >> 17, rem = i & 131071;
        int o = rem >> 10, kidx = rem & 1023;
        int ci = kidx >> 2, dh = (kidx >> 1) & 1, dw = kidx & 1;
        int py = par >> 1, px = par & 1;
        int kh = 2 * dh + 1 - py, kw = 2 * dw + 1 - px;
        float v = dw2[((ci * 128 + o) * 4 + kh) * 4 + kw];
        int dest = par * 131072 + (kidx >> 4) * 2048 + packoff(o, kidx & 15);
        wd2hi[dest] = tf32r(v);
    } else if (idx < 825856) {              // e2
        int c = idx - 825344;
        float s = 0.f;
        for (int d = 0; d < 64; d++) {
            float e = emb[c * 64 + d];
            s += e * e;
        }
        e2[c] = s;
    }
}

__global__ void pack_fwd(const float* __restrict__ ew2, float* __restrict__ w2hi,
                         float* __restrict__ w2lo,
                         const float* __restrict__ ew3, float* __restrict__ w3hi,
                         float* __restrict__ w3lo) {
    int idx = blockIdx.x * 256 + threadIdx.x;
    if (idx < 524288) {
        int m = idx >> 11, k = idx & 2047;
        float v = ew2[idx];
        float h = tf32r(v);
        int dest = ((m >> 7) * 128 + (k >> 4)) * 2048 + packoff(m & 127, k & 15);
        w2hi[dest] = h;
        w2lo[dest] = tf32r(v - h);
    } else if (idx < 524288 + 2097152) {
        int i = idx - 524288;
        int m = i >> 12, k = i & 4095;
        float v = ew3[i];
        float h = tf32r(v);
        int dest = ((m >> 7) * 256 + (k >> 4)) * 2048 + packoff(m & 127, k & 15);
        w3hi[dest] = h;
        w3lo[dest] = tf32r(v - h);
    }
}

// ------------------------------------------------------------------
// Warp-MMA tf32 implicit GEMM, fully-async 3-stage pipeline:
//   C[m][p] = sum_k W[m][k]*X[p][k]
// BM=128, BN=128, BK=16; 8 warps (2x4), warp tile 64x32.
// A: fragment-major packed gmem -> cp.async(16B).
// B: gather via cp.async(4B, zero-fill OOB) -> raw f32 in smem;
//    consumer converts to tf32 hi(/lo) in registers.
// MODE 0: stride-2 4x4 conv; MODE 2: convT parity (par = blockIdx.z).
// ------------------------------------------------------------------
struct MP {
    const float* x;
    const float* whi;
    const float* wlo;
    const float* bias;
    float* out;
    int Cin, Hin, Win, Mtot, Hout, Wout, K, sHWo, sW;
};

template <int MODE, int SPLITS, int ACT>
__global__ __launch_bounds__(256, 2) void mma_igemm(MP g) {
    extern __shared__ __align__(16) float sm[];
    constexpr int LDB = 136;
    constexpr int ALO = 2048;                         // lo A (SPLITS==3)
    constexpr int BRAW = (SPLITS == 3) ? 4096 : 2048;
    constexpr int STAGE = BRAW + 16 * LDB;            // 6272 / 4224 floats

    const int t = threadIdx.x;
    const int lane = t & 31;
    const int wid = t >> 5;
    const int p0 = blockIdx.x * 128;
    const int m0 = blockIdx.y * 128;
    const int par = (MODE == 2) ? blockIdx.z : 0;
    const int py = par >> 1, px = par & 1;
    const uint32_t sbase = smem_u32(sm);
    const float* __restrict__ whiP =
        g.whi + (size_t)par * g.Mtot * g.K +
        ((size_t)(m0 >> 7) * (g.K >> 4)) * 2048;
    const float* __restrict__ wloP =
        (SPLITS == 3)
            ? g.wlo + ((size_t)(m0 >> 7) * (g.K >> 4)) * 2048
            : whiP;

    // B loader role
    const int lm = t & 127;
    const int kq = (t >> 7) * 8;

    // im2col decode for p = p0 + lm
    const int p = p0 + lm;
    const int n = p >> g.sHWo;
    const int rem = p & ((1 << g.sHWo) - 1);
    const int ho = rem >> g.sW, wo = rem & ((1 << g.sW) - 1);
    const float* __restrict__ xn = g.x + (size_t)n * g.Cin * g.Hin * g.Win;
    const int HW = g.Hin * g.Win;

    int rowoff[4], iwv[4];
    bool okh[4], okw[4];
    if (MODE == 0) {
#pragma unroll
        for (int kh = 0; kh < 4; kh++) {
            int ih = 2 * ho - 1 + kh;
            okh[kh] = (unsigned)ih < (unsigned)g.Hin;
            rowoff[kh] = ih * g.Win;
        }
#pragma unroll
        for (int kw = 0; kw < 4; kw++) {
            int iw = 2 * wo - 1 + kw;
            okw[kw] = (unsigned)iw < (unsigned)g.Win;
            iwv[kw] = iw;
        }
    } else {
#pragma unroll
        for (int dh = 0; dh < 2; dh++) {
            int ih = ho + py - dh;
            okh[dh] = (unsigned)ih < (unsigned)g.Hin;
            rowoff[dh] = ih * g.Win;
        }
#pragma unroll
        for (int dw = 0; dw < 2; dw++) {
            int iw = wo + px - dw;
            okw[dw] = (unsigned)iw < (unsigned)g.Win;
            iwv[dw] = iw;
        }
    }

    const int wmh = wid >> 2;
    const int wn = (wid & 3) * 32;
    const int gp = lane >> 2;
    const int tg = lane & 3;

    float acc[4][4][4];
#pragma unroll
    for (int mi = 0; mi < 4; mi++)
#pragma unroll
        for (int ni = 0; ni < 4; ni++)
#pragma unroll
            for (int r = 0; r < 4; r++) acc[mi][ni][r] = 0.f;

    auto issueAB = [&](int c, int s) {
        // A (packed, 16B)
        uint32_t da = sbase + (uint32_t)(s * STAGE + t * 8) * 4;
        const float* srcH = whiP + (size_t)c * 2048 + t * 8;
        cpasync16(da, srcH);
        cpasync16(da + 16, srcH + 4);
        if (SPLITS == 3) {
            uint32_t d2 = sbase + (uint32_t)(s * STAGE + ALO + t * 8) * 4;
            const float* srcL = wloP + (size_t)c * 2048 + t * 8;
            cpasync16(d2, srcL);
            cpasync16(d2 + 16, srcL + 4);
        }
        // B (gather, 4B, zero-fill OOB)
        uint32_t dbase = sbase + (uint32_t)(s * STAGE + BRAW) * 4;
        if (MODE == 0) {
            const float* bp = xn + (size_t)c * HW;
#pragma unroll
            for (int j = 0; j < 8; j++) {
                int tap = kq + j;
                int kh = tap >> 2, kw = tap & 3;
                bool ok = okh[kh] && okw[kw];
                const float* src = bp + (ok ? rowoff[kh] + iwv[kw] : 0);
                cpasync4z(dbase + (uint32_t)(tap * LDB + lm) * 4, src,
                          ok ? 4u : 0u);
            }
        } else {
#pragma unroll
            for (int j = 0; j < 8; j++) {
                int tap = kq + j;
                int cl = tap >> 2, dd = tap & 3;
                int dh = dd >> 1, dw = dd & 1;
                bool ok = okh[dh] && okw[dw];
                const float* src =
                    xn + (size_t)(c * 4 + cl) * HW +
                    (ok ? rowoff[dh] + iwv[dw] : 0);
                cpasync4z(dbase + (uint32_t)(tap * LDB + lm) * 4, src,
                          ok ? 4u : 0u);
            }
        }
        CP_COMMIT();
    };

    auto compute = [&](int s) {
        const float* S = sm + s * STAGE;
        const float4* A4 = (const float4*)S;
#pragma unroll
        for (int ks = 0; ks < 2; ks++) {
            const int kb = ks * 8;
            float b[4][2], b2[4][2];
#pragma unroll
            for (int ni = 0; ni < 4; ni++) {
                int pc = wn + ni * 8 + gp;
                float r0 = S[BRAW + (kb + tg) * LDB + pc];
                float r1 = S[BRAW + (kb + tg + 4) * LDB + pc];
                b[ni][0] = tf32r(r0);
                b[ni][1] = tf32r(r1);
                if (SPLITS == 3) {
                    b2[ni][0] = tf32r(r0 - b[ni][0]);
                    b2[ni][1] = tf32r(r1 - b[ni][1]);
                }
            }
#pragma unroll
            for (int mi = 0; mi < 4; mi++) {
                const int fidx = ((wmh * 2 + ks) * 4 + mi) * 32 + lane;
                float4 af = A4[fidx];
                float a[4] = {af.x, af.y, af.z, af.w};
#pragma unroll
                for (int ni = 0; ni < 4; ni++) mma8(acc[mi][ni], a, b[ni]);
                if (SPLITS == 3) {
                    float4 af2 = A4[fidx + 512];   // ALO/4
                    float a2[4] = {af2.x, af2.y, af2.z, af2.w};
#pragma unroll
                    for (int ni = 0; ni < 4; ni++) mma8(acc[mi][ni], a2, b[ni]);
#pragma unroll
                    for (int ni = 0; ni < 4; ni++) mma8(acc[mi][ni], a, b2[ni]);
                }
            }
        }
    };

    const int nc = g.K >> 4;
    // 3-stage pipeline, 2 chunks in flight
    issueAB(0, 0);
    if (nc > 1) issueAB(1, 1);
    for (int c = 0; c < nc; c++) {
        if (c < nc - 1) CP_WAIT1(); else CP_WAIT0();
        __syncthreads();
        if (c + 2 < nc) issueAB(c + 2, (c + 2) % 3);
        compute(c % 3);
    }

    // epilogue
    const int HWo = 1 << g.sHWo;
    const int nn = p0 >> g.sHWo;
    const int rem0 = p0 & (HWo - 1);
#pragma unroll
    for (int mi = 0; mi < 4; mi++) {
        const int mA = m0 + wmh * 64 + mi * 16 + gp;
        const int mB = mA + 8;
        const float bA = g.bias[mA];
        const float bB = g.bias[mB];
#pragma unroll
        for (int ni = 0; ni < 4; ni++) {
            const int col = wn + ni * 8 + 2 * tg;
            float v0 = acc[mi][ni][0] + bA;
            float v1 = acc[mi][ni][1] + bA;
            float v2 = acc[mi][ni][2] + bB;
            float v3 = acc[mi][ni][3] + bB;
            if (ACT) {
                v0 = fmaxf(v0, 0.f); v1 = fmaxf(v1, 0.f);
                v2 = fmaxf(v2, 0.f); v3 = fmaxf(v3, 0.f);
            }
            if (MODE == 0) {
                float2 q0 = {v0, v1}, q1 = {v2, v3};
                *(float2*)&g.out[((size_t)nn * g.Mtot + mA) * HWo + rem0 + col] = q0;
                *(float2*)&g.out[((size_t)nn * g.Mtot + mB) * HWo + rem0 + col] = q1;
            } else {
                int rr = rem0 + col;
                int hh = rr >> g.sW, ww = rr & ((1 << g.sW) - 1);
                size_t r0 = ((size_t)nn * g.Mtot + mA) * g.Hout + 2 * hh + py;
                g.out[r0 * g.Wout + 2 * ww + px] = v0;
                g.out[r0 * g.Wout + 2 * (ww + 1) + px] = v1;
                size_t r1 = ((size_t)nn * g.Mtot + mB) * g.Hout + 2 * hh + py;
                g.out[r1 * g.Wout + 2 * ww + px] = v2;
                g.out[r1 * g.Wout + 2 * (ww + 1) + px] = v3;
            }
        }
    }
}

// ------------------------------------------------------------------
// SIMT implicit GEMM (1x1 conv only)
// ------------------------------------------------------------------
struct GP {
    const float* x;
    const float* wt;
    const float* bias;
    float* out;
    int Cin, Hin, Win, M, K, sHWo, sW;
};

template <int ACT>
__global__ __launch_bounds__(256) void igemm1x1(GP g) {
    __shared__ __align__(16) float As[16][64];
    __shared__ __align__(16) float Bs[16][64];
    const int t = threadIdx.x;
    const int p0 = blockIdx.x * 64;
    const int m0 = blockIdx.y * 64;
    const int lc = t & 63, lr = t >> 6;
    const int tx = t & 15, ty = t >> 4;

    const int pB = p0 + lc;
    const int nB = pB >> g.sHWo;
    const int remB = pB & ((1 << g.sHWo) - 1);
    const float* __restrict__ xn = g.x + (size_t)nB * g.Cin * g.Hin * g.Win;

    float acc[4][4];
#pragma unroll
    for (int i = 0; i < 4; i++)
#pragma unroll
        for (int j = 0; j < 4; j++) acc[i][j] = 0.f;

    for (int k0 = 0; k0 < g.K; k0 += 16) {
#pragma unroll
        for (int j = 0; j < 4; j++) {
            int r = lr + 4 * j;
            As[r][lc] = g.wt[(size_t)(k0 + r) * g.M + m0 + lc];
            Bs[r][lc] = xn[(size_t)(k0 + r) * g.Win + remB];
        }
        __syncthreads();
#pragma unroll
        for (int kk = 0; kk < 16; kk++) {
            float4 a4 = *(const float4*)&As[kk][ty * 4];
            float4 b4 = *(const float4*)&Bs[kk][tx * 4];
            float av[4] = {a4.x, a4.y, a4.z, a4.w};
            float bv[4] = {b4.x, b4.y, b4.z, b4.w};
#pragma unroll
            for (int i = 0; i < 4; i++)
#pragma unroll
                for (int j = 0; j < 4; j++) acc[i][j] += av[i] * bv[j];
        }
        __syncthreads();
    }

    const int HWo = 1 << g.sHWo;
#pragma unroll
    for (int j = 0; j < 4; j++) {
        int p = p0 + tx * 4 + j;
        int nn = p >> g.sHWo;
        int rm = p & (HWo - 1);
#pragma unroll
        for (int i = 0; i < 4; i++) {
            int m = m0 + ty * 4 + i;
            float v = acc[i][j] + g.bias[m];
            if (ACT == 1) v = fmaxf(v, 0.f);
            g.out[((size_t)nn * g.M + m) * HWo + rm] = v;
        }
    }
}

// ------------------------------------------------------------------
// VQ v2 (dot-product form, float4 broadcast) + loss
// ------------------------------------------------------------------
__global__ __launch_bounds__(128) void vq_kernel(
    const float* __restrict__ ze, const float* __restrict__ emb,
    const float* __restrict__ e2, float* __restrict__ zq,
    float* __restrict__ partial) {
    __shared__ float es[8192];
    __shared__ float e2s[128];
    __shared__ float red[128];
    const int t = threadIdx.x;
    const int pos = blockIdx.x * 128 + t;
    const int n = pos >> 10;
    const int hw = pos & 1023;

    float xv[64];
    const float* zp = ze + (size_t)n * 65536 + hw;
    float x2 = 0.f;
#pragma unroll
    for (int d = 0; d < 64; d++) {
        xv[d] = zp[(size_t)d * 1024];
        x2 += xv[d] * xv[d];
    }

    float best = 3.0e38f;
    int bidx = 0;
    for (int c0 = 0; c0 < 512; c0 += 128) {
        __syncthreads();
        {
            const float4* src = (const float4*)(emb + c0 * 64);
            float4* dst = (float4*)es;
            for (int i = t; i < 2048; i += 128) dst[i] = src[i];
            e2s[t] = e2[c0 + t];
        }
        __syncthreads();
        for (int c = 0; c < 128; c++) {
            float dot = 0.f;
            const float4* ep = (const float4*)(es + c * 64);
#pragma unroll
            for (int q = 0; q < 16; q++) {
                float4 e4 = ep[q];
                dot += xv[q * 4] * e4.x + xv[q * 4 + 1] * e4.y +
                       xv[q * 4 + 2] * e4.z + xv[q * 4 + 3] * e4.w;
            }
            float sc = e2s[c] - 2.f * dot;
            if (sc < best) { best = sc; bidx = c0 + c; }
        }
    }
    const float* e = emb + (size_t)bidx * 64;
    float* q = zq + (size_t)n * 65536 + hw;
#pragma unroll
    for (int d = 0; d < 64; d++) q[(size_t)d * 1024] = e[d];

    red[t] = x2 + best;
    __syncthreads();
    for (int s = 64; s > 0; s >>= 1) {
        if (t < s) red[t] += red[t + s];
        __syncthreads();
    }
    if (t == 0) partial[blockIdx.x] = red[0];
}

__global__ void vq_loss_kernel(const float* __restrict__ partial,
                               float* __restrict__ out_loss) {
    __shared__ float red[256];
    int t = threadIdx.x;
    red[t] = partial[t];
    __syncthreads();
    for (int s = 128; s > 0; s >>= 1) {
        if (t < s) red[t] += red[t + s];
        __syncthreads();
    }
    if (t == 0) out_loss[0] = red[0] * (2.0f / 2097152.0f);
}

// ------------------------------------------------------------------
// convT3 v2: smem-tiled direct + sigmoid
// ------------------------------------------------------------------
__global__ __launch_bounds__(256) void convt3_v2(
    const float* __restrict__ in, const float* __restrict__ w,
    const float* __restrict__ b, float* __restrict__ out) {
    extern __shared__ float s[];
    float* ws = s;             // 6144
    float* dat = s + 6144;     // 3*32*128 = 12288
    const int t = threadIdx.x;
    const int yq = blockIdx.y;
    const int n = blockIdx.z;
    for (int i = t; i < 6144; i += 256) ws[i] = w[i];

    const int py = t >> 7;
    const int xq = t & 127;
    float acc0[3], acc1[3];
#pragma unroll
    for (int ch = 0; ch < 3; ch++) { acc0[ch] = b[ch]; acc1[ch] = b[ch]; }

    const float* xn = in + (size_t)n * 2097152;
    for (int c0 = 0; c0 < 128; c0 += 32) {
        __syncthreads();
        for (int i = t; i < 12288; i += 256) {
            int r = i >> 12;
            int cc = (i >> 7) & 31;
            int wv = i & 127;
            int h = yq - 1 + r;
            dat[i] = ((unsigned)h < 128u)
                         ? xn[(size_t)(c0 + cc) * 16384 + h * 128 + wv] : 0.f;
        }
        __syncthreads();
        for (int cc = 0; cc < 32; cc++) {
            const float* wsc = ws + (c0 + cc) * 48;
#pragma unroll
            for (int dh = 0; dh < 2; dh++) {
                const int r = py + 1 - dh;
                const float* dr = dat + (r << 12) + (cc << 7);
                float v0 = dr[xq];
                float vm = (xq > 0) ? dr[xq - 1] : 0.f;
                float vp = (xq < 127) ? dr[xq + 1] : 0.f;
                const int kh = 2 * dh + 1 - py;
#pragma unroll
                for (int ch = 0; ch < 3; ch++) {
                    const float* wk = wsc + ch * 16 + kh * 4;
                    acc0[ch] += v0 * wk[1] + vm * wk[3];
                    acc1[ch] += vp * wk[0] + v0 * wk[2];
                }
            }
        }
    }
    const int y = 2 * yq + py;
#pragma unroll
    for (int ch = 0; ch < 3; ch++) {
        float2 q;
        q.x = 1.f / (1.f + expf(-acc0[ch]));
        q.y = 1.f / (1.f + expf(-acc1[ch]));
        *(float2*)&out[(((size_t)n * 3 + ch) << 16) + y * 256 + 2 * xq] = q;
    }
}

// ------------------------------------------------------------------
// Launch
// ------------------------------------------------------------------
extern "C" void kernel_launch(void* const* d_in, const int* in_sizes, int n_in,
                              void* d_out, int out_size) {
    (void)in_sizes; (void)n_in; (void)out_size;
    const float* x   = (const float*)d_in[0];
    const float* ew1 = (const float*)d_in[1];
    const float* eb1 = (const float*)d_in[2];
    const float* ew2 = (const float*)d_in[3];
    const float* eb2 = (const float*)d_in[4];
    const float* ew3 = (const float*)d_in[5];
    const float* eb3 = (const float*)d_in[6];
    const float* pw  = (const float*)d_in[7];
    const float* pb  = (const float*)d_in[8];
    const float* emb = (const float*)d_in[9];
    const float* dw1 = (const float*)d_in[10];
    const float* db1 = (const float*)d_in[11];
    const float* dw2 = (const float*)d_in[12];
    const float* db2 = (const float*)d_in[13];
    const float* dw3 = (const float*)d_in[14];
    const float* db3 = (const float*)d_in[15];
    float* out = (float*)d_out;

    float *arena, *wtp, *part, *e2;
    float *w1hi, *w1lo, *w2hi, *w2lo, *w3hi, *w3lo, *wd1hi, *wd2hi;
    cudaGetSymbolAddress((void**)&arena, g_arena);
    cudaGetSymbolAddress((void**)&wtp, g_wtp);
    cudaGetSymbolAddress((void**)&w1hi, g_w1hi);
    cudaGetSymbolAddress((void**)&w1lo, g_w1lo);
    cudaGetSymbolAddress((void**)&w2hi, g_w2hi);
    cudaGetSymbolAddress((void**)&w2lo, g_w2lo);
    cudaGetSymbolAddress((void**)&w3hi, g_w3hi);
    cudaGetSymbolAddress((void**)&w3lo, g_w3lo);
    cudaGetSymbolAddress((void**)&wd1hi, g_wd1hi);
    cudaGetSymbolAddress((void**)&wd2hi, g_wd2hi);
    cudaGetSymbolAddress((void**)&e2, g_vqe2);
    cudaGetSymbolAddress((void**)&part, g_vqpart);

    float* h1  = arena;
    float* d2b = arena;
    float* h2  = arena + 67108864;
    float* d1b = arena + 67108864;
    float* h3  = arena + 100663296;
    float* ze  = arena + 117440512;
    float* zq  = arena + 119537664;

    // smem: S3 stage = 6272 fl -> 3 stages = 75264 B
    //       S1 stage = 4224 fl -> 3 stages = 50688 B
    const int SM3 = 3 * 6272 * 4;
    const int SM1 = 3 * 4224 * 4;
    const int SMT3 = (6144 + 12288) * 4;
    cudaFuncSetAttribute(mma_igemm<0, 3, 1>,
                         cudaFuncAttributeMaxDynamicSharedMemorySize, SM3);
    cudaFuncSetAttribute(mma_igemm<2, 1, 1>,
                         cudaFuncAttributeMaxDynamicSharedMemorySize, SM1);
    cudaFuncSetAttribute(convt3_v2,
                         cudaFuncAttributeMaxDynamicSharedMemorySize, SMT3);

    // 2 transform launches (capture slot -> conv2)
    xform_misc<<<(825856 + 255) / 256, 256>>>(ew1, w1hi, w1lo, pw, wtp,
                                              dw1, wd1hi, dw2, wd2hi, emb, e2);
    pack_fwd<<<(2621440 + 255) / 256, 256>>>(ew2, w2hi, w2lo, ew3, w3hi, w3lo);

    MP m;
    // conv1 (3xTF32): x[32,3,256,256] -> h1[32,128,128,128]
    m.x = x; m.whi = w1hi; m.wlo = w1lo; m.bias = eb1; m.out = h1;
    m.Cin = 3; m.Hin = 256; m.Win = 256; m.Mtot = 128;
    m.Hout = 128; m.Wout = 128; m.K = 48; m.sHWo = 14; m.sW = 7;
    mma_igemm<0, 3, 1><<<dim3(4096, 1), 256, SM3>>>(m);

    // conv2 (3xTF32): h1 -> h2[32,256,64,64]
    m.x = h1; m.whi = w2hi; m.wlo = w2lo; m.bias = eb2; m.out = h2;
    m.Cin = 128; m.Hin = 128; m.Win = 128; m.Mtot = 256;
    m.Hout = 64; m.Wout = 64; m.K = 2048; m.sHWo = 12; m.sW = 6;
    mma_igemm<0, 3, 1><<<dim3(1024, 2), 256, SM3>>>(m);

    // conv3 (3xTF32): h2 -> h3[32,512,32,32]
    m.x = h2; m.whi = w3hi; m.wlo = w3lo; m.bias = eb3; m.out = h3;
    m.Cin = 256; m.Hin = 64; m.Win = 64; m.Mtot = 512;
    m.Hout = 32; m.Wout = 32; m.K = 4096; m.sHWo = 10; m.sW = 5;
    mma_igemm<0, 3, 1><<<dim3(256, 4), 256, SM3>>>(m);

    // pre-VQ 1x1 (SIMT fp32): h3 -> ze
    GP g;
    g.x = h3; g.wt = wtp; g.bias = pb; g.out = ze;
    g.Cin = 512; g.Hin = 1; g.Win = 1024; g.M = 64;
    g.K = 512; g.sHWo = 10; g.sW = 0;
    igemm1x1<0><<<dim3(32768 / 64, 1), 256>>>(g);

    // VQ
    vq_kernel<<<256, 128>>>(ze, emb, e2, zq, part);
    vq_loss_kernel<<<1, 256>>>(part, out + 6291456);

    // convT1 (1xTF32): zq -> d1[32,256,64,64]  (4 pars via grid z)
    m.x = zq; m.whi = wd1hi; m.wlo = wd1hi; m.bias = db1; m.out = d1b;
    m.Cin = 64; m.Hin = 32; m.Win = 32; m.Mtot = 256;
    m.Hout = 64; m.Wout = 64; m.K = 256; m.sHWo = 10; m.sW = 5;
    mma_igemm<2, 1, 1><<<dim3(256, 2, 4), 256, SM1>>>(m);

    // convT2 (1xTF32): d1 -> d2[32,128,128,128]  (4 pars via grid z)
    m.x = d1b; m.whi = wd2hi; m.wlo = wd2hi; m.bias = db2; m.out = d2b;
    m.Cin = 256; m.Hin = 64; m.Win = 64; m.Mtot = 128;
    m.Hout = 128; m.Wout = 128; m.K = 1024; m.sHWo = 12; m.sW = 6;
    mma_igemm<2, 1, 1><<<dim3(1024, 1, 4), 256, SM1>>>(m);

    // convT3 v2 (smem-tiled) + sigmoid
    convt3_v2<<<dim3(1, 128, 32), 256, SMT3>>>(d2b, dw3, db3, out);
}

// round 10
// speedup vs baseline: 2.0885x; 1.0006x over previous
#include <cuda_runtime.h>
#include <math.h>
#include <stdint.h>

// ------------------------------------------------------------------
// Scratch (device globals). Arena lifetime-aliased: h1/d2, h2/d1.
// ------------------------------------------------------------------
__device__ float g_arena[121634816];
__device__ float g_wtp[32768];       // 1x1 SIMT [k][m]
__device__ float g_w1hi[6144];       // conv1  packed frag-major hi/lo
__device__ float g_w1lo[6144];
__device__ float g_w2hi[524288];     // conv2 packed
__device__ float g_w2lo[524288];
__device__ float g_w3hi[2097152];    // conv3 packed
__device__ float g_w3lo[2097152];
__device__ float g_wd1hi[262144];    // convT1 [par] packed (hi only)
__device__ float g_wd2hi[524288];    // convT2 [par] packed (hi only)
__device__ float g_vqe2[512];
__device__ float g_vqpart[256];

// ------------------------------------------------------------------
// Helpers
// ------------------------------------------------------------------
__device__ __forceinline__ float tf32r(float v) {
    uint32_t u;
    asm("cvt.rna.tf32.f32 %0, %1;" : "=r"(u) : "f"(v));
    return __uint_as_float(u);
}
__device__ __forceinline__ uint32_t smem_u32(const void* p) {
    uint32_t a;
    asm("{ .reg .u64 t; cvta.to.shared.u64 t, %1; cvt.u32.u64 %0, t; }"
        : "=r"(a) : "l"(p));
    return a;
}
__device__ __forceinline__ void cpasync16(uint32_t dst, const void* src) {
    asm volatile("cp.async.cg.shared.global [%0], [%1], 16;"
                 :: "r"(dst), "l"(src));
}
// 4B cp.async with zero-fill when pred=0 (src not accessed)
__device__ __forceinline__ void cpasync4z(uint32_t dst, const void* src,
                                          uint32_t sz) {
    asm volatile("cp.async.ca.shared.global [%0], [%1], 4, %2;"
                 :: "r"(dst), "l"(src), "r"(sz));
}
#define CP_COMMIT() asm volatile("cp.async.commit_group;" ::: "memory")
#define CP_WAIT1()  asm volatile("cp.async.wait_group 1;" ::: "memory")
#define CP_WAIT0()  asm volatile("cp.async.wait_group 0;" ::: "memory")

__device__ __forceinline__ void mma8(float* d, const float* a, const float* b) {
    asm volatile(
        "mma.sync.aligned.m16n8k8.row.col.f32.tf32.tf32.f32 "
        "{%0,%1,%2,%3},{%4,%5,%6,%7},{%8,%9},{%0,%1,%2,%3};"
        : "+f"(d[0]), "+f"(d[1]), "+f"(d[2]), "+f"(d[3])
        : "r"(__float_as_uint(a[0])), "r"(__float_as_uint(a[1])),
          "r"(__float_as_uint(a[2])), "r"(__float_as_uint(a[3])),
          "r"(__float_as_uint(b[0])), "r"(__float_as_uint(b[1])));
}

// fragment-major pack offset within a (128m x 16k) block of A.
__device__ __forceinline__ int packoff(int mr, int kk) {
    int wmh = mr >> 6, mi = (mr >> 4) & 3, r8 = (mr >> 3) & 1, gp = mr & 7;
    int ks = kk >> 3, j2 = (kk >> 2) & 1, tg = kk & 3;
    return ((((wmh * 2 + ks) * 4 + mi) * 32) + gp * 4 + tg) * 4 + (r8 + 2 * j2);
}

// ------------------------------------------------------------------
// Weight transforms (2 launches total)
// ------------------------------------------------------------------
__global__ void xform_misc(const float* __restrict__ ew1, float* __restrict__ w1hi,
                           float* __restrict__ w1lo,
                           const float* __restrict__ pw, float* __restrict__ wtp,
                           const float* __restrict__ dw1, float* __restrict__ wd1hi,
                           const float* __restrict__ dw2, float* __restrict__ wd2hi,
                           const float* __restrict__ emb, float* __restrict__ e2) {
    int idx = blockIdx.x * 256 + threadIdx.x;
    if (idx < 6144) {                       // conv1: Cout=128, K=48
        int m = idx / 48, k = idx - m * 48;
        float v = ew1[idx];
        float h = tf32r(v);
        int dest = (k >> 4) * 2048 + packoff(m & 127, k & 15);
        w1hi[dest] = h;
        w1lo[dest] = tf32r(v - h);
    } else if (idx < 38912) {               // 1x1: Cout=64, CK=512
        int i = idx - 6144;
        int co = i / 512, k = i - co * 512;
        wtp[k * 64 + co] = pw[i];
    } else if (idx < 301056) {              // convT1: Cin=64, Cout=256, K=256
        int i = idx - 38912;
        int par = i >> 16, rem = i & 65535;
        int o = rem >> 8, kidx = rem & 255;
        int ci = kidx >> 2, dh = (kidx >> 1) & 1, dw = kidx & 1;
        int py = par >> 1, px = par & 1;
        int kh = 2 * dh + 1 - py, kw = 2 * dw + 1 - px;
        float v = dw1[((ci * 256 + o) * 4 + kh) * 4 + kw];
        int dest = par * 65536 + ((o >> 7) * 16 + (kidx >> 4)) * 2048 +
                   packoff(o & 127, kidx & 15);
        wd1hi[dest] = tf32r(v);
    } else if (idx < 825344) {              // convT2: Cin=256, Cout=128, K=1024
        int i = idx - 301056;
        int par = i >> 17, rem = i & 131071;
        int o = rem >> 10, kidx = rem & 1023;
        int ci = kidx >> 2, dh = (kidx >> 1) & 1, dw = kidx & 1;
        int py = par >> 1, px = par & 1;
        int kh = 2 * dh + 1 - py, kw = 2 * dw + 1 - px;
        float v = dw2[((ci * 128 + o) * 4 + kh) * 4 + kw];
        int dest = par * 131072 + (kidx >> 4) * 2048 + packoff(o, kidx & 15);
        wd2hi[dest] = tf32r(v);
    } else if (idx < 825856) {              // e2
        int c = idx - 825344;
        float s = 0.f;
        for (int d = 0; d < 64; d++) {
            float e = emb[c * 64 + d];
            s += e * e;
        }
        e2[c] = s;
    }
}

__global__ void pack_fwd(const float* __restrict__ ew2, float* __restrict__ w2hi,
                         float* __restrict__ w2lo,
                         const float* __restrict__ ew3, float* __restrict__ w3hi,
                         float* __restrict__ w3lo) {
    int idx = blockIdx.x * 256 + threadIdx.x;
    if (idx < 524288) {
        int m = idx >> 11, k = idx & 2047;
        float v = ew2[idx];
        float h = tf32r(v);
        int dest = ((m >> 7) * 128 + (k >> 4)) * 2048 + packoff(m & 127, k & 15);
        w2hi[dest] = h;
        w2lo[dest] = tf32r(v - h);
    } else if (idx < 524288 + 2097152) {
        int i = idx - 524288;
        int m = i >> 12, k = i & 4095;
        float v = ew3[i];
        float h = tf32r(v);
        int dest = ((m >> 7) * 256 + (k >> 4)) * 2048 + packoff(m & 127, k & 15);
        w3hi[dest] = h;
        w3lo[dest] = tf32r(v - h);
    }
}

// ------------------------------------------------------------------
// Warp-MMA tf32 implicit GEMM, fully-async 3-stage pipeline:
//   C[m][p] = sum_k W[m][k]*X[p][k]
// BM=128, BN=128, BK=16; 8 warps (2x4), warp tile 64x32.
// A: fragment-major packed gmem -> cp.async(16B).
// B: gather via cp.async(4B, zero-fill OOB) -> raw f32 in smem;
//    consumer converts to tf32 hi(/lo) in registers.
// MODE 0: stride-2 4x4 conv; MODE 2: convT parity (par = blockIdx.z).
// ------------------------------------------------------------------
struct MP {
    const float* x;
    const float* whi;
    const float* wlo;
    const float* bias;
    float* out;
    int Cin, Hin, Win, Mtot, Hout, Wout, K, sHWo, sW;
};

template <int MODE, int SPLITS, int ACT>
__global__ __launch_bounds__(256, 2) void mma_igemm(MP g) {
    extern __shared__ __align__(16) float sm[];
    constexpr int LDB = 136;
    constexpr int ALO = 2048;                         // lo A (SPLITS==3)
    constexpr int BRAW = (SPLITS == 3) ? 4096 : 2048;
    constexpr int STAGE = BRAW + 16 * LDB;            // 6272 / 4224 floats

    const int t = threadIdx.x;
    const int lane = t & 31;
    const int wid = t >> 5;
    const int p0 = blockIdx.x * 128;
    const int m0 = blockIdx.y * 128;
    const int par = (MODE == 2) ? blockIdx.z : 0;
    const int py = par >> 1, px = par & 1;
    const uint32_t sbase = smem_u32(sm);
    const float* __restrict__ whiP =
        g.whi + (size_t)par * g.Mtot * g.K +
        ((size_t)(m0 >> 7) * (g.K >> 4)) * 2048;
    const float* __restrict__ wloP =
        (SPLITS == 3)
            ? g.wlo + ((size_t)(m0 >> 7) * (g.K >> 4)) * 2048
            : whiP;

    // B loader role
    const int lm = t & 127;
    const int kq = (t >> 7) * 8;

    // im2col decode for p = p0 + lm
    const int p = p0 + lm;
    const int n = p >> g.sHWo;
    const int rem = p & ((1 << g.sHWo) - 1);
    const int ho = rem >> g.sW, wo = rem & ((1 << g.sW) - 1);
    const float* __restrict__ xn = g.x + (size_t)n * g.Cin * g.Hin * g.Win;
    const int HW = g.Hin * g.Win;

    int rowoff[4], iwv[4];
    bool okh[4], okw[4];
    if (MODE == 0) {
#pragma unroll
        for (int kh = 0; kh < 4; kh++) {
            int ih = 2 * ho - 1 + kh;
            okh[kh] = (unsigned)ih < (unsigned)g.Hin;
            rowoff[kh] = ih * g.Win;
        }
#pragma unroll
        for (int kw = 0; kw < 4; kw++) {
            int iw = 2 * wo - 1 + kw;
            okw[kw] = (unsigned)iw < (unsigned)g.Win;
            iwv[kw] = iw;
        }
    } else {
#pragma unroll
        for (int dh = 0; dh < 2; dh++) {
            int ih = ho + py - dh;
            okh[dh] = (unsigned)ih < (unsigned)g.Hin;
            rowoff[dh] = ih * g.Win;
        }
#pragma unroll
        for (int dw = 0; dw < 2; dw++) {
            int iw = wo + px - dw;
            okw[dw] = (unsigned)iw < (unsigned)g.Win;
            iwv[dw] = iw;
        }
    }

    const int wmh = wid >> 2;
    const int wn = (wid & 3) * 32;
    const int gp = lane >> 2;
    const int tg = lane & 3;

    float acc[4][4][4];
#pragma unroll
    for (int mi = 0; mi < 4; mi++)
#pragma unroll
        for (int ni = 0; ni < 4; ni++)
#pragma unroll
            for (int r = 0; r < 4; r++) acc[mi][ni][r] = 0.f;

    auto issueAB = [&](int c, int s) {
        // A (packed, 16B)
        uint32_t da = sbase + (uint32_t)(s * STAGE + t * 8) * 4;
        const float* srcH = whiP + (size_t)c * 2048 + t * 8;
        cpasync16(da, srcH);
        cpasync16(da + 16, srcH + 4);
        if (SPLITS == 3) {
            uint32_t d2 = sbase + (uint32_t)(s * STAGE + ALO + t * 8) * 4;
            const float* srcL = wloP + (size_t)c * 2048 + t * 8;
            cpasync16(d2, srcL);
            cpasync16(d2 + 16, srcL + 4);
        }
        // B (gather, 4B, zero-fill OOB)
        uint32_t dbase = sbase + (uint32_t)(s * STAGE + BRAW) * 4;
        if (MODE == 0) {
            const float* bp = xn + (size_t)c * HW;
#pragma unroll
            for (int j = 0; j < 8; j++) {
                int tap = kq + j;
                int kh = tap >> 2, kw = tap & 3;
                bool ok = okh[kh] && okw[kw];
                const float* src = bp + (ok ? rowoff[kh] + iwv[kw] : 0);
                cpasync4z(dbase + (uint32_t)(tap * LDB + lm) * 4, src,
                          ok ? 4u : 0u);
            }
        } else {
#pragma unroll
            for (int j = 0; j < 8; j++) {
                int tap = kq + j;
                int cl = tap >> 2, dd = tap & 3;
                int dh = dd >> 1, dw = dd & 1;
                bool ok = okh[dh] && okw[dw];
                const float* src =
                    xn + (size_t)(c * 4 + cl) * HW +
                    (ok ? rowoff[dh] + iwv[dw] : 0);
                cpasync4z(dbase + (uint32_t)(tap * LDB + lm) * 4, src,
                          ok ? 4u : 0u);
            }
        }
        CP_COMMIT();
    };

    auto compute = [&](int s) {
        const float* S = sm + s * STAGE;
        const float4* A4 = (const float4*)S;
#pragma unroll
        for (int ks = 0; ks < 2; ks++) {
            const int kb = ks * 8;
            float b[4][2], b2[4][2];
#pragma unroll
            for (int ni = 0; ni < 4; ni++) {
                int pc = wn + ni * 8 + gp;
                float r0 = S[BRAW + (kb + tg) * LDB + pc];
                float r1 = S[BRAW + (kb + tg + 4) * LDB + pc];
                b[ni][0] = tf32r(r0);
                b[ni][1] = tf32r(r1);
                if (SPLITS == 3) {
                    b2[ni][0] = tf32r(r0 - b[ni][0]);
                    b2[ni][1] = tf32r(r1 - b[ni][1]);
                }
            }
#pragma unroll
            for (int mi = 0; mi < 4; mi++) {
                const int fidx = ((wmh * 2 + ks) * 4 + mi) * 32 + lane;
                float4 af = A4[fidx];
                float a[4] = {af.x, af.y, af.z, af.w};
#pragma unroll
                for (int ni = 0; ni < 4; ni++) mma8(acc[mi][ni], a, b[ni]);
                if (SPLITS == 3) {
                    float4 af2 = A4[fidx + 512];   // ALO/4
                    float a2[4] = {af2.x, af2.y, af2.z, af2.w};
#pragma unroll
                    for (int ni = 0; ni < 4; ni++) mma8(acc[mi][ni], a2, b[ni]);
#pragma unroll
                    for (int ni = 0; ni < 4; ni++) mma8(acc[mi][ni], a, b2[ni]);
                }
            }
        }
    };

    const int nc = g.K >> 4;
    // 3-stage pipeline, 2 chunks in flight
    issueAB(0, 0);
    if (nc > 1) issueAB(1, 1);
    for (int c = 0; c < nc; c++) {
        if (c < nc - 1) CP_WAIT1(); else CP_WAIT0();
        __syncthreads();
        if (c + 2 < nc) issueAB(c + 2, (c + 2) % 3);
        compute(c % 3);
    }

    // epilogue
    const int HWo = 1 << g.sHWo;
    const int nn = p0 >> g.sHWo;
    const int rem0 = p0 & (HWo - 1);
#pragma unroll
    for (int mi = 0; mi < 4; mi++) {
        const int mA = m0 + wmh * 64 + mi * 16 + gp;
        const int mB = mA + 8;
        const float bA = g.bias[mA];
        const float bB = g.bias[mB];
#pragma unroll
        for (int ni = 0; ni < 4; ni++) {
            const int col = wn + ni * 8 + 2 * tg;
            float v0 = acc[mi][ni][0] + bA;
            float v1 = acc[mi][ni][1] + bA;
            float v2 = acc[mi][ni][2] + bB;
            float v3 = acc[mi][ni][3] + bB;
            if (ACT) {
                v0 = fmaxf(v0, 0.f); v1 = fmaxf(v1, 0.f);
                v2 = fmaxf(v2, 0.f); v3 = fmaxf(v3, 0.f);
            }
            if (MODE == 0) {
                float2 q0 = {v0, v1}, q1 = {v2, v3};
                *(float2*)&g.out[((size_t)nn * g.Mtot + mA) * HWo + rem0 + col] = q0;
                *(float2*)&g.out[((size_t)nn * g.Mtot + mB) * HWo + rem0 + col] = q1;
            } else {
                int rr = rem0 + col;
                int hh = rr >> g.sW, ww = rr & ((1 << g.sW) - 1);
                size_t r0 = ((size_t)nn * g.Mtot + mA) * g.Hout + 2 * hh + py;
                g.out[r0 * g.Wout + 2 * ww + px] = v0;
                g.out[r0 * g.Wout + 2 * (ww + 1) + px] = v1;
                size_t r1 = ((size_t)nn * g.Mtot + mB) * g.Hout + 2 * hh + py;
                g.out[r1 * g.Wout + 2 * ww + px] = v2;
                g.out[r1 * g.Wout + 2 * (ww + 1) + px] = v3;
            }
        }
    }
}

// ------------------------------------------------------------------
// SIMT implicit GEMM (1x1 conv only)
// ------------------------------------------------------------------
struct GP {
    const float* x;
    const float* wt;
    const float* bias;
    float* out;
    int Cin, Hin, Win, M, K, sHWo, sW;
};

template <int ACT>
__global__ __launch_bounds__(256) void igemm1x1(GP g) {
    __shared__ __align__(16) float As[16][64];
    __shared__ __align__(16) float Bs[16][64];
    const int t = threadIdx.x;
    const int p0 = blockIdx.x * 64;
    const int m0 = blockIdx.y * 64;
    const int lc = t & 63, lr = t >> 6;
    const int tx = t & 15, ty = t >> 4;

    const int pB = p0 + lc;
    const int nB = pB >> g.sHWo;
    const int remB = pB & ((1 << g.sHWo) - 1);
    const float* __restrict__ xn = g.x + (size_t)nB * g.Cin * g.Hin * g.Win;

    float acc[4][4];
#pragma unroll
    for (int i = 0; i < 4; i++)
#pragma unroll
        for (int j = 0; j < 4; j++) acc[i][j] = 0.f;

    for (int k0 = 0; k0 < g.K; k0 += 16) {
#pragma unroll
        for (int j = 0; j < 4; j++) {
            int r = lr + 4 * j;
            As[r][lc] = g.wt[(size_t)(k0 + r) * g.M + m0 + lc];
            Bs[r][lc] = xn[(size_t)(k0 + r) * g.Win + remB];
        }
        __syncthreads();
#pragma unroll
        for (int kk = 0; kk < 16; kk++) {
            float4 a4 = *(const float4*)&As[kk][ty * 4];
            float4 b4 = *(const float4*)&Bs[kk][tx * 4];
            float av[4] = {a4.x, a4.y, a4.z, a4.w};
            float bv[4] = {b4.x, b4.y, b4.z, b4.w};
#pragma unroll
            for (int i = 0; i < 4; i++)
#pragma unroll
                for (int j = 0; j < 4; j++) acc[i][j] += av[i] * bv[j];
        }
        __syncthreads();
    }

    const int HWo = 1 << g.sHWo;
#pragma unroll
    for (int j = 0; j < 4; j++) {
        int p = p0 + tx * 4 + j;
        int nn = p >> g.sHWo;
        int rm = p & (HWo - 1);
#pragma unroll
        for (int i = 0; i < 4; i++) {
            int m = m0 + ty * 4 + i;
            float v = acc[i][j] + g.bias[m];
            if (ACT == 1) v = fmaxf(v, 0.f);
            g.out[((size_t)nn * g.M + m) * HWo + rm] = v;
        }
    }
}

// ------------------------------------------------------------------
// VQ v2 (dot-product form, float4 broadcast) + loss
// ------------------------------------------------------------------
__global__ __launch_bounds__(128) void vq_kernel(
    const float* __restrict__ ze, const float* __restrict__ emb,
    const float* __restrict__ e2, float* __restrict__ zq,
    float* __restrict__ partial) {
    __shared__ float es[8192];
    __shared__ float e2s[128];
    __shared__ float red[128];
    const int t = threadIdx.x;
    const int pos = blockIdx.x * 128 + t;
    const int n = pos >> 10;
    const int hw = pos & 1023;

    float xv[64];
    const float* zp = ze + (size_t)n * 65536 + hw;
    float x2 = 0.f;
#pragma unroll
    for (int d = 0; d < 64; d++) {
        xv[d] = zp[(size_t)d * 1024];
        x2 += xv[d] * xv[d];
    }

    float best = 3.0e38f;
    int bidx = 0;
    for (int c0 = 0; c0 < 512; c0 += 128) {
        __syncthreads();
        {
            const float4* src = (const float4*)(emb + c0 * 64);
            float4* dst = (float4*)es;
            for (int i = t; i < 2048; i += 128) dst[i] = src[i];
            e2s[t] = e2[c0 + t];
        }
        __syncthreads();
        for (int c = 0; c < 128; c++) {
            float dot = 0.f;
            const float4* ep = (const float4*)(es + c * 64);
#pragma unroll
            for (int q = 0; q < 16; q++) {
                float4 e4 = ep[q];
                dot += xv[q * 4] * e4.x + xv[q * 4 + 1] * e4.y +
                       xv[q * 4 + 2] * e4.z + xv[q * 4 + 3] * e4.w;
            }
            float sc = e2s[c] - 2.f * dot;
            if (sc < best) { best = sc; bidx = c0 + c; }
        }
    }
    const float* e = emb + (size_t)bidx * 64;
    float* q = zq + (size_t)n * 65536 + hw;
#pragma unroll
    for (int d = 0; d < 64; d++) q[(size_t)d * 1024] = e[d];

    red[t] = x2 + best;
    __syncthreads();
    for (int s = 64; s > 0; s >>= 1) {
        if (t < s) red[t] += red[t + s];
        __syncthreads();
    }
    if (t == 0) partial[blockIdx.x] = red[0];
}

__global__ void vq_loss_kernel(const float* __restrict__ partial,
                               float* __restrict__ out_loss) {
    __shared__ float red[256];
    int t = threadIdx.x;
    red[t] = partial[t];
    __syncthreads();
    for (int s = 128; s > 0; s >>= 1) {
        if (t < s) red[t] += red[t + s];
        __syncthreads();
    }
    if (t == 0) out_loss[0] = red[0] * (2.0f / 2097152.0f);
}

// ------------------------------------------------------------------
// convT3 v2: smem-tiled direct + sigmoid
// ------------------------------------------------------------------
__global__ __launch_bounds__(256) void convt3_v2(
    const float* __restrict__ in, const float* __restrict__ w,
    const float* __restrict__ b, float* __restrict__ out) {
    extern __shared__ float s[];
    float* ws = s;             // 6144
    float* dat = s + 6144;     // 3*32*128 = 12288
    const int t = threadIdx.x;
    const int yq = blockIdx.y;
    const int n = blockIdx.z;
    for (int i = t; i < 6144; i += 256) ws[i] = w[i];

    const int py = t >> 7;
    const int xq = t & 127;
    float acc0[3], acc1[3];
#pragma unroll
    for (int ch = 0; ch < 3; ch++) { acc0[ch] = b[ch]; acc1[ch] = b[ch]; }

    const float* xn = in + (size_t)n * 2097152;
    for (int c0 = 0; c0 < 128; c0 += 32) {
        __syncthreads();
        for (int i = t; i < 12288; i += 256) {
            int r = i >> 12;
            int cc = (i >> 7) & 31;
            int wv = i & 127;
            int h = yq - 1 + r;
            dat[i] = ((unsigned)h < 128u)
                         ? xn[(size_t)(c0 + cc) * 16384 + h * 128 + wv] : 0.f;
        }
        __syncthreads();
        for (int cc = 0; cc < 32; cc++) {
            const float* wsc = ws + (c0 + cc) * 48;
#pragma unroll
            for (int dh = 0; dh < 2; dh++) {
                const int r = py + 1 - dh;
                const float* dr = dat + (r << 12) + (cc << 7);
                float v0 = dr[xq];
                float vm = (xq > 0) ? dr[xq - 1] : 0.f;
                float vp = (xq < 127) ? dr[xq + 1] : 0.f;
                const int kh = 2 * dh + 1 - py;
#pragma unroll
                for (int ch = 0; ch < 3; ch++) {
                    const float* wk = wsc + ch * 16 + kh * 4;
                    acc0[ch] += v0 * wk[1] + vm * wk[3];
                    acc1[ch] += vp * wk[0] + v0 * wk[2];
                }
            }
        }
    }
    const int y = 2 * yq + py;
#pragma unroll
    for (int ch = 0; ch < 3; ch++) {
        float2 q;
        q.x = 1.f / (1.f + expf(-acc0[ch]));
        q.y = 1.f / (1.f + expf(-acc1[ch]));
        *(float2*)&out[(((size_t)n * 3 + ch) << 16) + y * 256 + 2 * xq] = q;
    }
}

// ------------------------------------------------------------------
// Launch
// ------------------------------------------------------------------
extern "C" void kernel_launch(void* const* d_in, const int* in_sizes, int n_in,
                              void* d_out, int out_size) {
    (void)in_sizes; (void)n_in; (void)out_size;
    const float* x   = (const float*)d_in[0];
    const float* ew1 = (const float*)d_in[1];
    const float* eb1 = (const float*)d_in[2];
    const float* ew2 = (const float*)d_in[3];
    const float* eb2 = (const float*)d_in[4];
    const float* ew3 = (const float*)d_in[5];
    const float* eb3 = (const float*)d_in[6];
    const float* pw  = (const float*)d_in[7];
    const float* pb  = (const float*)d_in[8];
    const float* emb = (const float*)d_in[9];
    const float* dw1 = (const float*)d_in[10];
    const float* db1 = (const float*)d_in[11];
    const float* dw2 = (const float*)d_in[12];
    const float* db2 = (const float*)d_in[13];
    const float* dw3 = (const float*)d_in[14];
    const float* db3 = (const float*)d_in[15];
    float* out = (float*)d_out;

    float *arena, *wtp, *part, *e2;
    float *w1hi, *w1lo, *w2hi, *w2lo, *w3hi, *w3lo, *wd1hi, *wd2hi;
    cudaGetSymbolAddress((void**)&arena, g_arena);
    cudaGetSymbolAddress((void**)&wtp, g_wtp);
    cudaGetSymbolAddress((void**)&w1hi, g_w1hi);
    cudaGetSymbolAddress((void**)&w1lo, g_w1lo);
    cudaGetSymbolAddress((void**)&w2hi, g_w2hi);
    cudaGetSymbolAddress((void**)&w2lo, g_w2lo);
    cudaGetSymbolAddress((void**)&w3hi, g_w3hi);
    cudaGetSymbolAddress((void**)&w3lo, g_w3lo);
    cudaGetSymbolAddress((void**)&wd1hi, g_wd1hi);
    cudaGetSymbolAddress((void**)&wd2hi, g_wd2hi);
    cudaGetSymbolAddress((void**)&e2, g_vqe2);
    cudaGetSymbolAddress((void**)&part, g_vqpart);

    float* h1  = arena;
    float* d2b = arena;
    float* h2  = arena + 67108864;
    float* d1b = arena + 67108864;
    float* h3  = arena + 100663296;
    float* ze  = arena + 117440512;
    float* zq  = arena + 119537664;

    // smem: S3 stage = 6272 fl -> 3 stages = 75264 B
    //       S1 stage = 4224 fl -> 3 stages = 50688 B
    const int SM3 = 3 * 6272 * 4;
    const int SM1 = 3 * 4224 * 4;
    const int SMT3 = (6144 + 12288) * 4;
    cudaFuncSetAttribute(mma_igemm<0, 3, 1>,
                         cudaFuncAttributeMaxDynamicSharedMemorySize, SM3);
    cudaFuncSetAttribute(mma_igemm<2, 1, 1>,
                         cudaFuncAttributeMaxDynamicSharedMemorySize, SM1);
    cudaFuncSetAttribute(convt3_v2,
                         cudaFuncAttributeMaxDynamicSharedMemorySize, SMT3);

    // 2 transform launches (capture slot -> conv2)
    xform_misc<<<(825856 + 255) / 256, 256>>>(ew1, w1hi, w1lo, pw, wtp,
                                              dw1, wd1hi, dw2, wd2hi, emb, e2);
    pack_fwd<<<(2621440 + 255) / 256, 256>>>(ew2, w2hi, w2lo, ew3, w3hi, w3lo);

    MP m;
    // conv1 (3xTF32): x[32,3,256,256] -> h1[32,128,128,128]
    m.x = x; m.whi = w1hi; m.wlo = w1lo; m.bias = eb1; m.out = h1;
    m.Cin = 3; m.Hin = 256; m.Win = 256; m.Mtot = 128;
    m.Hout = 128; m.Wout = 128; m.K = 48; m.sHWo = 14; m.sW = 7;
    mma_igemm<0, 3, 1><<<dim3(4096, 1), 256, SM3>>>(m);

    // conv2 (3xTF32): h1 -> h2[32,256,64,64]
    m.x = h1; m.whi = w2hi; m.wlo = w2lo; m.bias = eb2; m.out = h2;
    m.Cin = 128; m.Hin = 128; m.Win = 128; m.Mtot = 256;
    m.Hout = 64; m.Wout = 64; m.K = 2048; m.sHWo = 12; m.sW = 6;
    mma_igemm<0, 3, 1><<<dim3(1024, 2), 256, SM3>>>(m);

    // conv3 (3xTF32): h2 -> h3[32,512,32,32]
    m.x = h2; m.whi = w3hi; m.wlo = w3lo; m.bias = eb3; m.out = h3;
    m.Cin = 256; m.Hin = 64; m.Win = 64; m.Mtot = 512;
    m.Hout = 32; m.Wout = 32; m.K = 4096; m.sHWo = 10; m.sW = 5;
    mma_igemm<0, 3, 1><<<dim3(256, 4), 256, SM3>>>(m);

    // pre-VQ 1x1 (SIMT fp32): h3 -> ze
    GP g;
    g.x = h3; g.wt = wtp; g.bias = pb; g.out = ze;
    g.Cin = 512; g.Hin = 1; g.Win = 1024; g.M = 64;
    g.K = 512; g.sHWo = 10; g.sW = 0;
    igemm1x1<0><<<dim3(32768 / 64, 1), 256>>>(g);

    // VQ
    vq_kernel<<<256, 128>>>(ze, emb, e2, zq, part);
    vq_loss_kernel<<<1, 256>>>(part, out + 6291456);

    // convT1 (1xTF32): zq -> d1[32,256,64,64]  (4 pars via grid z)
    m.x = zq; m.whi = wd1hi; m.wlo = wd1hi; m.bias = db1; m.out = d1b;
    m.Cin = 64; m.Hin = 32; m.Win = 32; m.Mtot = 256;
    m.Hout = 64; m.Wout = 64; m.K = 256; m.sHWo = 10; m.sW = 5;
    mma_igemm<2, 1, 1><<<dim3(256, 2, 4), 256, SM1>>>(m);

    // convT2 (1xTF32): d1 -> d2[32,128,128,128]  (4 pars via grid z)
    m.x = d1b; m.whi = wd2hi; m.wlo = wd2hi; m.bias = db2; m.out = d2b;
    m.Cin = 256; m.Hin = 64; m.Win = 64; m.Mtot = 128;
    m.Hout = 128; m.Wout = 128; m.K = 1024; m.sHWo = 12; m.sW = 6;
    mma_igemm<2, 1, 1><<<dim3(1024, 1, 4), 256, SM1>>>(m);

    // convT3 v2 (smem-tiled) + sigmoid
    convt3_v2<<<dim3(1, 128, 32), 256, SMT3>>>(d2b, dw3, db3, out);
}